// round 5
// baseline (speedup 1.0000x reference)
#include <cuda_runtime.h>
#include <cstdint>

#define H   768
#define NH_ 12
#define HD_ 64
#define B_  16
#define T_  512
#define NROWS (B_ * T_)
#define SCALING 2.0f

// -------- device scratch --------
__device__ float g_xt  [(size_t)NROWS * H];
__device__ float g_weff_q[H * H];
__device__ float g_weff_v[H * H];
__device__ float g_wkt [H * H];
__device__ float g_wot [H * H];
__device__ float g_q [(size_t)NROWS * H];
__device__ float g_k [(size_t)NROWS * H];
__device__ float g_v [(size_t)NROWS * H];
__device__ float g_ao[(size_t)NROWS * H];
__device__ int   g_idx[B_ * T_];
__device__ int   g_vcnt[B_];

// ============================================================
// helpers
// ============================================================
__device__ __forceinline__ float rna_tf32(float x) {
    uint32_t u;
    asm("cvt.rna.tf32.f32 %0, %1;" : "=r"(u) : "f"(x));
    return __uint_as_float(u);
}

__device__ __forceinline__ void mma_tf32(float* d, const uint32_t* a, const uint32_t* b) {
    asm volatile(
        "mma.sync.aligned.m16n8k8.row.col.f32.tf32.tf32.f32 "
        "{%0,%1,%2,%3}, {%4,%5,%6,%7}, {%8,%9}, {%0,%1,%2,%3};"
        : "+f"(d[0]), "+f"(d[1]), "+f"(d[2]), "+f"(d[3])
        : "r"(a[0]), "r"(a[1]), "r"(a[2]), "r"(a[3]), "r"(b[0]), "r"(b[1]));
}
__device__ __forceinline__ void mma_tf32f(float* d, const float* a, const float* b) {
    asm volatile(
        "mma.sync.aligned.m16n8k8.row.col.f32.tf32.tf32.f32 "
        "{%0,%1,%2,%3}, {%4,%5,%6,%7}, {%8,%9}, {%0,%1,%2,%3};"
        : "+f"(d[0]), "+f"(d[1]), "+f"(d[2]), "+f"(d[3])
        : "r"(__float_as_uint(a[0])), "r"(__float_as_uint(a[1])),
          "r"(__float_as_uint(a[2])), "r"(__float_as_uint(a[3])),
          "r"(__float_as_uint(b[0])), "r"(__float_as_uint(b[1])));
}

__device__ __forceinline__ uint32_t smem_u32(const void* p) {
    uint32_t a;
    asm("{ .reg .u64 t; cvta.to.shared.u64 t, %1; cvt.u32.u64 %0, t; }"
        : "=r"(a) : "l"(p));
    return a;
}

__device__ __forceinline__ void cp_async16(uint32_t dst, const void* src) {
    asm volatile("cp.async.ca.shared.global [%0], [%1], 16;" :: "r"(dst), "l"(src));
}
#define CP_COMMIT() asm volatile("cp.async.commit_group;" ::: "memory")
#define CP_WAIT(n)  asm volatile("cp.async.wait_group %0;" :: "n"(n) : "memory")

// polynomial 2^t for t <= 0 (FMA pipe). rel err ~1e-5.
__device__ __forceinline__ float exp2p(float t) {
    t = fmaxf(t, -126.f);
    float fi = floorf(t);
    float f  = t - fi;
    float p  = 0.0001540353f;
    p = fmaf(p, f, 0.0013333558f);
    p = fmaf(p, f, 0.0096181291f);
    p = fmaf(p, f, 0.0555041087f);
    p = fmaf(p, f, 0.2402265070f);
    p = fmaf(p, f, 0.6931471806f);
    p = fmaf(p, f, 1.0f);
    int ei = (int)fi;
    return p * __int_as_float((ei + 127) << 23);
}
#define LOG2E 1.4426950408889634f

// ============================================================
// prep kernels
// ============================================================
__global__ void cvt_rna_kernel(const float* __restrict__ in, float* __restrict__ out, int n) {
    int i = blockIdx.x * 256 + threadIdx.x;
    if (i < n) out[i] = rna_tf32(in[i]);
}

template <int OUTSEL>
__global__ void weff_kernel(const float* __restrict__ W,
                            const float* __restrict__ A,
                            const float* __restrict__ Bm) {
    int idx = blockIdx.x * 256 + threadIdx.x;
    if (idx >= H * H) return;
    int j = idx / H, h = idx % H;
    float acc = W[idx];
#pragma unroll
    for (int r = 0; r < 4; r++)
        acc = fmaf(SCALING * Bm[j * 4 + r], A[r * H + h], acc);
    float* out = (OUTSEL == 1) ? g_weff_q : g_weff_v;
    out[idx] = rna_tf32(acc);
}

__global__ void compact_kernel(const int* __restrict__ mask) {
    int b = blockIdx.x;
    int lane = threadIdx.x;
    int base = 0;
    for (int c = 0; c < T_ / 32; c++) {
        int key = c * 32 + lane;
        int v = (mask[b * T_ + key] != 0);
        unsigned bal = __ballot_sync(0xffffffffu, v);
        int pos = base + __popc(bal & ((1u << lane) - 1u));
        if (v) g_idx[b * T_ + pos] = key;
        base += __popc(bal);
    }
    if (lane == 0) g_vcnt[b] = base;
}

// ============================================================
// tf32 GEMM: C[n,j] = sum_h A[n,h]*W[j,h] + bias[j]
// CTA tile 128x256, BK=16, 3-stage cp.async, 256 thr (8 warps,
// each 64x64). grid.x = 3*nsel, grid.y = 64.
// ============================================================
#define GP 20
#define A_STG (128 * GP)          // 2560 floats
#define W_STG (256 * GP)          // 5120 floats
#define STG   (A_STG + W_STG)     // 7680 floats = 30 KB
#define GNITER (H / 16)           // 48
#define GEMM_SMEM (3 * STG * 4)   // 92160 B

extern __shared__ float gsm[];

__global__ __launch_bounds__(256, 1)
void gemm_mma(const float* __restrict__ A,
              const float* W0, const float* W1, const float* W2,
              const float* b0, const float* b1, const float* b2,
              float* C0, float* C1, float* C2) {
    const int sel = blockIdx.x / 3;
    const float* W    = (sel == 0) ? W0 : (sel == 1) ? W1 : W2;
    const float* bias = (sel == 0) ? b0 : (sel == 1) ? b1 : b2;
    float*       C    = (sel == 0) ? C0 : (sel == 1) ? C1 : C2;

    const int tid  = threadIdx.x;
    const int wid  = tid >> 5;
    const int lane = tid & 31;
    const int lr   = lane >> 2;
    const int lc   = lane & 3;
    const int rowBase = blockIdx.y * 128;
    const int colBase = (blockIdx.x % 3) * 256;
    const int mwarp = (wid & 1) * 64;
    const int nwarp = (wid >> 1) * 64;

    const uint32_t sbase = smem_u32(gsm);

    // load slots
    int arow[2], ac4[2], wrow[4], wc4[4];
#pragma unroll
    for (int i = 0; i < 2; i++) { int e = tid + i * 256; arow[i] = e >> 2; ac4[i] = (e & 3) << 2; }
#pragma unroll
    for (int i = 0; i < 4; i++) { int e = tid + i * 256; wrow[i] = e >> 2; wc4[i] = (e & 3) << 2; }

    auto load_stage = [&](int it, int st) {
        const int k0 = it * 16;
        const uint32_t base = sbase + (uint32_t)(st * STG) * 4;
#pragma unroll
        for (int i = 0; i < 2; i++)
            cp_async16(base + (uint32_t)(arow[i] * GP + ac4[i]) * 4,
                       A + (size_t)(rowBase + arow[i]) * H + k0 + ac4[i]);
#pragma unroll
        for (int i = 0; i < 4; i++)
            cp_async16(base + (uint32_t)(A_STG + wrow[i] * GP + wc4[i]) * 4,
                       W + (size_t)(colBase + wrow[i]) * H + k0 + wc4[i]);
        CP_COMMIT();
    };

    float acc[4][8][4];
#pragma unroll
    for (int mt = 0; mt < 4; mt++)
#pragma unroll
        for (int nt = 0; nt < 8; nt++)
#pragma unroll
            for (int i = 0; i < 4; i++) acc[mt][nt][i] = 0.f;

    load_stage(0, 0);
    load_stage(1, 1);

    for (int it = 0; it < GNITER; it++) {
        CP_WAIT(1);
        __syncthreads();
        if (it + 2 < GNITER) load_stage(it + 2, (it + 2) % 3);

        const float* cAf = gsm + (it % 3) * STG;
        const float* cWf = cAf + A_STG;
#pragma unroll
        for (int ks = 0; ks < 2; ks++) {
            const int kb = ks * 8 + lc;
            float af[4][4], bf[8][2];
#pragma unroll
            for (int mt = 0; mt < 4; mt++) {
                const int m0 = mwarp + mt * 16 + lr;
                af[mt][0] = cAf[m0 * GP + kb];
                af[mt][1] = cAf[(m0 + 8) * GP + kb];
                af[mt][2] = cAf[m0 * GP + kb + 4];
                af[mt][3] = cAf[(m0 + 8) * GP + kb + 4];
            }
#pragma unroll
            for (int nt = 0; nt < 8; nt++) {
                const int n0 = nwarp + nt * 8 + lr;
                bf[nt][0] = cWf[n0 * GP + kb];
                bf[nt][1] = cWf[n0 * GP + kb + 4];
            }
#pragma unroll
            for (int mt = 0; mt < 4; mt++)
#pragma unroll
                for (int nt = 0; nt < 8; nt++)
                    mma_tf32f(acc[mt][nt], af[mt], bf[nt]);
        }
    }
    __syncthreads();

#pragma unroll
    for (int mt = 0; mt < 4; mt++) {
        const int r0 = rowBase + mwarp + mt * 16 + lr;
#pragma unroll
        for (int nt = 0; nt < 8; nt++) {
            const int c0 = colBase + nwarp + nt * 8 + lc * 2;
            const float bb0 = __ldg(&bias[c0]);
            const float bb1 = __ldg(&bias[c0 + 1]);
            float2 v0 = { acc[mt][nt][0] + bb0, acc[mt][nt][1] + bb1 };
            float2 v1 = { acc[mt][nt][2] + bb0, acc[mt][nt][3] + bb1 };
            *reinterpret_cast<float2*>(&C[(size_t)r0 * H + c0])       = v0;
            *reinterpret_cast<float2*>(&C[(size_t)(r0 + 8) * H + c0]) = v1;
        }
    }
}

// ============================================================
// Attention v3: tensor-core S=QK^T and P*V (tf32 mma.sync),
// compacted keys, fp32 softmax with poly exp2.
// 128 threads (4 warps), 64 q-rows/block; warp owns 16 q-rows.
// grid = (8, 12, 16).
// ============================================================
#define QP 68          // pitch for sQ / sKP (Q, K, P tiles)
#define VP 72          // pitch for sV (conflict-free B-fragment loads)
#define ATT_SMEM ((64 * QP * 2 + 64 * VP) * 4 + T_ * 4)

extern __shared__ float asm_[];

__global__ __launch_bounds__(128)
void attn_kernel(const float* __restrict__ Q, const float* __restrict__ K,
                 const float* __restrict__ V, float* __restrict__ O) {
    float* sQ  = asm_;
    float* sKP = sQ + 64 * QP;      // K tile; reused for P
    float* sV  = sKP + 64 * QP;
    int*  sIdx = (int*)(sV + 64 * VP);

    const int qt = blockIdx.x;
    const int nh = blockIdx.y;
    const int b  = blockIdx.z;
    const int tid  = threadIdx.x;
    const int wid  = tid >> 5;
    const int lane = tid & 31;
    const int lr   = lane >> 2;
    const int lc   = lane & 3;
    const int qr   = wid * 16 + lr;      // this thread's first q-row

    const int vcnt = g_vcnt[b];
    for (int i = tid; i < T_; i += 128) sIdx[i] = g_idx[b * T_ + i];

    const float* Qb = Q + (size_t)(b * T_ + qt * 64) * H + nh * HD_;
    const float* Kb = K + (size_t)(b * T_) * H + nh * HD_;
    const float* Vb = V + (size_t)(b * T_) * H + nh * HD_;

    // load Q (pre-scaled by 1/8, rna-rounded)
#pragma unroll
    for (int it = 0; it < 16; it++) {
        int e = tid + it * 128;
        int row = e >> 5, c2 = (e & 31) << 1;
        float2 v = *reinterpret_cast<const float2*>(&Qb[row * H + c2]);
        float2 o = { rna_tf32(v.x * 0.125f), rna_tf32(v.y * 0.125f) };
        *reinterpret_cast<float2*>(&sQ[row * QP + c2]) = o;
    }
    __syncthreads();

    // preload Q fragments (persistent across key tiles)
    float aq[8][4];
#pragma unroll
    for (int ks = 0; ks < 8; ks++) {
        const int k0 = ks * 8;
        aq[ks][0] = sQ[qr * QP + k0 + lc];
        aq[ks][1] = sQ[(qr + 8) * QP + k0 + lc];
        aq[ks][2] = sQ[qr * QP + k0 + lc + 4];
        aq[ks][3] = sQ[(qr + 8) * QP + k0 + lc + 4];
    }

    float m0 = -1e30f, m1 = -1e30f, l0 = 0.f, l1 = 0.f;
    float accO[8][4];
#pragma unroll
    for (int nt = 0; nt < 8; nt++)
#pragma unroll
        for (int i = 0; i < 4; i++) accO[nt][i] = 0.f;

    const int ntiles = (vcnt + 63) >> 6;
    for (int kt = 0; kt < ntiles; kt++) {
        __syncthreads();   // protect sKP (P) / sV of previous tile
        const int base = kt << 6;
        const int nval = min(64, vcnt - base);

        // gather K/V (rna-rounded)
#pragma unroll
        for (int it = 0; it < 16; it++) {
            int e = tid + it * 128;
            int row = e >> 5, c2 = (e & 31) << 1;
            int grow = sIdx[base + ((row < nval) ? row : 0)];
            float2 kv = *reinterpret_cast<const float2*>(&Kb[(size_t)grow * H + c2]);
            float2 vv = *reinterpret_cast<const float2*>(&Vb[(size_t)grow * H + c2]);
            float2 ko = { rna_tf32(kv.x), rna_tf32(kv.y) };
            float2 vo = { rna_tf32(vv.x), rna_tf32(vv.y) };
            *reinterpret_cast<float2*>(&sKP[row * QP + c2]) = ko;
            *reinterpret_cast<float2*>(&sV[row * VP + c2])  = vo;
        }
        __syncthreads();

        // S = Q K^T  (64 mma per warp)
        float s[8][4];
#pragma unroll
        for (int nt = 0; nt < 8; nt++)
#pragma unroll
            for (int i = 0; i < 4; i++) s[nt][i] = 0.f;
#pragma unroll
        for (int nt = 0; nt < 8; nt++) {
            const int n0 = nt * 8 + lr;
#pragma unroll
            for (int ks = 0; ks < 8; ks++) {
                const int k0 = ks * 8;
                float bf[2];
                bf[0] = sKP[n0 * QP + k0 + lc];
                bf[1] = sKP[n0 * QP + k0 + lc + 4];
                mma_tf32f(s[nt], aq[ks], bf);
            }
        }

        // mask invalid columns
#pragma unroll
        for (int nt = 0; nt < 8; nt++) {
            const int c = nt * 8 + 2 * lc;
            if (c     >= nval) { s[nt][0] = -1e9f; s[nt][2] = -1e9f; }
            if (c + 1 >= nval) { s[nt][1] = -1e9f; s[nt][3] = -1e9f; }
        }

        // online softmax (rows qr and qr+8)
        float mx0 = s[0][0], mx1 = s[0][2];
#pragma unroll
        for (int nt = 0; nt < 8; nt++) {
            mx0 = fmaxf(mx0, fmaxf(s[nt][0], s[nt][1]));
            mx1 = fmaxf(mx1, fmaxf(s[nt][2], s[nt][3]));
        }
        mx0 = fmaxf(mx0, __shfl_xor_sync(0xffffffffu, mx0, 1));
        mx0 = fmaxf(mx0, __shfl_xor_sync(0xffffffffu, mx0, 2));
        mx1 = fmaxf(mx1, __shfl_xor_sync(0xffffffffu, mx1, 1));
        mx1 = fmaxf(mx1, __shfl_xor_sync(0xffffffffu, mx1, 2));

        float mn0 = fmaxf(m0, mx0), mn1 = fmaxf(m1, mx1);
        float cr0 = exp2p((m0 - mn0) * LOG2E);
        float cr1 = exp2p((m1 - mn1) * LOG2E);
        m0 = mn0; m1 = mn1;

        float ps0 = 0.f, ps1 = 0.f;
#pragma unroll
        for (int nt = 0; nt < 8; nt++) {
            s[nt][0] = exp2p((s[nt][0] - mn0) * LOG2E);
            s[nt][1] = exp2p((s[nt][1] - mn0) * LOG2E);
            s[nt][2] = exp2p((s[nt][2] - mn1) * LOG2E);
            s[nt][3] = exp2p((s[nt][3] - mn1) * LOG2E);
            ps0 += s[nt][0] + s[nt][1];
            ps1 += s[nt][2] + s[nt][3];
        }
        ps0 += __shfl_xor_sync(0xffffffffu, ps0, 1);
        ps0 += __shfl_xor_sync(0xffffffffu, ps0, 2);
        ps1 += __shfl_xor_sync(0xffffffffu, ps1, 1);
        ps1 += __shfl_xor_sync(0xffffffffu, ps1, 2);
        l0 = l0 * cr0 + ps0;
        l1 = l1 * cr1 + ps1;
#pragma unroll
        for (int nt = 0; nt < 8; nt++) {
            accO[nt][0] *= cr0; accO[nt][1] *= cr0;
            accO[nt][2] *= cr1; accO[nt][3] *= cr1;
        }

        __syncthreads();   // all warps done reading sKP as K

        // store P (rna-rounded) transposed into fragment-loadable layout
#pragma unroll
        for (int nt = 0; nt < 8; nt++) {
            const int c = nt * 8 + 2 * lc;
            float2 p0 = { rna_tf32(s[nt][0]), rna_tf32(s[nt][1]) };
            float2 p1 = { rna_tf32(s[nt][2]), rna_tf32(s[nt][3]) };
            *reinterpret_cast<float2*>(&sKP[qr * QP + c])       = p0;
            *reinterpret_cast<float2*>(&sKP[(qr + 8) * QP + c]) = p1;
        }
        __syncwarp();

        // preload P fragments (warp reads only its own 16 rows)
        float ap[8][4];
#pragma unroll
        for (int ks = 0; ks < 8; ks++) {
            const int k0 = ks * 8;
            ap[ks][0] = sKP[qr * QP + k0 + lc];
            ap[ks][1] = sKP[(qr + 8) * QP + k0 + lc];
            ap[ks][2] = sKP[qr * QP + k0 + lc + 4];
            ap[ks][3] = sKP[(qr + 8) * QP + k0 + lc + 4];
        }

        // O += P * V  (64 mma per warp)
#pragma unroll
        for (int nt = 0; nt < 8; nt++) {
            const int n0 = nt * 8 + lr;
#pragma unroll
            for (int ks = 0; ks < 8; ks++) {
                const int k0 = ks * 8;
                float bv[2];
                bv[0] = sV[(k0 + lc) * VP + n0];
                bv[1] = sV[(k0 + lc + 4) * VP + n0];
                mma_tf32f(accO[nt], ap[ks], bv);
            }
        }
    }

    // write O (rna-rounded for the O-proj GEMM)
    float* Ob = O + (size_t)(b * T_ + qt * 64) * H + nh * HD_;
    const float i0 = 1.0f / l0, i1 = 1.0f / l1;
#pragma unroll
    for (int nt = 0; nt < 8; nt++) {
        const int c = nt * 8 + 2 * lc;
        float2 o0 = { rna_tf32(accO[nt][0] * i0), rna_tf32(accO[nt][1] * i0) };
        float2 o1 = { rna_tf32(accO[nt][2] * i1), rna_tf32(accO[nt][3] * i1) };
        *reinterpret_cast<float2*>(&Ob[qr * H + c])       = o0;
        *reinterpret_cast<float2*>(&Ob[(qr + 8) * H + c]) = o1;
    }
}

// ============================================================
// launch
// ============================================================
extern "C" void kernel_launch(void* const* d_in, const int* in_sizes, int n_in,
                              void* d_out, int out_size) {
    (void)in_sizes; (void)n_in; (void)out_size;
    const float* x  = (const float*)d_in[0];
    const int*  mask = (const int*) d_in[1];
    const float* Wq = (const float*)d_in[2];
    const float* bq = (const float*)d_in[3];
    const float* Aq = (const float*)d_in[4];
    const float* Bq = (const float*)d_in[5];
    const float* Wk = (const float*)d_in[6];
    const float* bk = (const float*)d_in[7];
    const float* Wv = (const float*)d_in[8];
    const float* bv = (const float*)d_in[9];
    const float* Av = (const float*)d_in[10];
    const float* Bv = (const float*)d_in[11];
    const float* Wo = (const float*)d_in[12];
    const float* bo = (const float*)d_in[13];
    float* out = (float*)d_out;

    float *pxt, *pweff_q, *pweff_v, *pwkt, *pwot, *pq, *pk, *pv, *pao;
    cudaGetSymbolAddress((void**)&pxt, g_xt);
    cudaGetSymbolAddress((void**)&pweff_q, g_weff_q);
    cudaGetSymbolAddress((void**)&pweff_v, g_weff_v);
    cudaGetSymbolAddress((void**)&pwkt, g_wkt);
    cudaGetSymbolAddress((void**)&pwot, g_wot);
    cudaGetSymbolAddress((void**)&pq, g_q);
    cudaGetSymbolAddress((void**)&pk, g_k);
    cudaGetSymbolAddress((void**)&pv, g_v);
    cudaGetSymbolAddress((void**)&pao, g_ao);

    static bool attr_set = false;
    if (!attr_set) {
        cudaFuncSetAttribute(gemm_mma,
            cudaFuncAttributeMaxDynamicSharedMemorySize, GEMM_SMEM);
        cudaFuncSetAttribute(attn_kernel,
            cudaFuncAttributeMaxDynamicSharedMemorySize, ATT_SMEM);
        attr_set = true;
    }

    // prep
    cvt_rna_kernel<<<(NROWS * H + 255) / 256, 256>>>(x, pxt, NROWS * H);
    cvt_rna_kernel<<<(H * H + 255) / 256, 256>>>(Wk, pwkt, H * H);
    cvt_rna_kernel<<<(H * H + 255) / 256, 256>>>(Wo, pwot, H * H);
    weff_kernel<1><<<(H * H + 255) / 256, 256>>>(Wq, Aq, Bq);
    weff_kernel<2><<<(H * H + 255) / 256, 256>>>(Wv, Av, Bv);
    compact_kernel<<<B_, 32>>>(mask);

    // fused Q/K/V projection
    gemm_mma<<<dim3(9, NROWS / 128), 256, GEMM_SMEM>>>(
        pxt, pweff_q, pwkt, pweff_v, bq, bk, bv, pq, pk, pv);

    // attention
    attn_kernel<<<dim3(T_ / 64, NH_, B_), 128, ATT_SMEM>>>(pq, pk, pv, pao);

    // output projection
    gemm_mma<<<dim3(3, NROWS / 128), 256, GEMM_SMEM>>>(
        pao, pwot, pwot, pwot, bo, bo, bo, out, out, out);
}

// round 6
// speedup vs baseline: 1.5257x; 1.5257x over previous
#include <cuda_runtime.h>
#include <cstdint>

#define H   768
#define NH_ 12
#define HD_ 64
#define B_  16
#define T_  512
#define NROWS (B_ * T_)
#define SCALING 2.0f

// -------- device scratch --------
__device__ float g_xt  [(size_t)NROWS * H];
__device__ float g_weff_q[H * H];
__device__ float g_weff_v[H * H];
__device__ float g_wkt [H * H];
__device__ float g_wot [H * H];
__device__ float g_q [(size_t)NROWS * H];
__device__ float g_k [(size_t)NROWS * H];
__device__ float g_v [(size_t)NROWS * H];
__device__ float g_ao[(size_t)NROWS * H];
__device__ int   g_idx[B_ * T_];
__device__ int   g_vcnt[B_];

// ============================================================
// helpers
// ============================================================
__device__ __forceinline__ float rna_tf32(float x) {
    uint32_t u;
    asm("cvt.rna.tf32.f32 %0, %1;" : "=r"(u) : "f"(x));
    return __uint_as_float(u);
}

__device__ __forceinline__ void mma_tf32f(float* d, const float* a, const float* b) {
    asm volatile(
        "mma.sync.aligned.m16n8k8.row.col.f32.tf32.tf32.f32 "
        "{%0,%1,%2,%3}, {%4,%5,%6,%7}, {%8,%9}, {%0,%1,%2,%3};"
        : "+f"(d[0]), "+f"(d[1]), "+f"(d[2]), "+f"(d[3])
        : "r"(__float_as_uint(a[0])), "r"(__float_as_uint(a[1])),
          "r"(__float_as_uint(a[2])), "r"(__float_as_uint(a[3])),
          "r"(__float_as_uint(b[0])), "r"(__float_as_uint(b[1])));
}

__device__ __forceinline__ uint32_t smem_u32(const void* p) {
    uint32_t a;
    asm("{ .reg .u64 t; cvta.to.shared.u64 t, %1; cvt.u32.u64 %0, t; }"
        : "=r"(a) : "l"(p));
    return a;
}

__device__ __forceinline__ void cp_async16(uint32_t dst, const void* src) {
    asm volatile("cp.async.ca.shared.global [%0], [%1], 16;" :: "r"(dst), "l"(src));
}
#define CP_COMMIT() asm volatile("cp.async.commit_group;" ::: "memory")
#define CP_WAIT(n)  asm volatile("cp.async.wait_group %0;" :: "n"(n) : "memory")

// polynomial 2^t for t <= 0 (FMA pipe). rel err ~1e-5.
__device__ __forceinline__ float exp2p(float t) {
    t = fmaxf(t, -126.f);
    float fi = floorf(t);
    float f  = t - fi;
    float p  = 0.0001540353f;
    p = fmaf(p, f, 0.0013333558f);
    p = fmaf(p, f, 0.0096181291f);
    p = fmaf(p, f, 0.0555041087f);
    p = fmaf(p, f, 0.2402265070f);
    p = fmaf(p, f, 0.6931471806f);
    p = fmaf(p, f, 1.0f);
    int ei = (int)fi;
    return p * __int_as_float((ei + 127) << 23);
}
#define LOG2E 1.4426950408889634f

// ============================================================
// fused prep: cvt x/Wk/Wo, weff q/v, mask compaction — 1 launch
// ============================================================
#define XBLK  (NROWS * H / 256)   // 24576
#define WBLK  (H * H / 256)       // 2304

__global__ __launch_bounds__(256)
void prep_kernel(const float* __restrict__ x,
                 const float* __restrict__ Wk, const float* __restrict__ Wo,
                 const float* __restrict__ Wq, const float* __restrict__ Aq,
                 const float* __restrict__ Bq,
                 const float* __restrict__ Wv, const float* __restrict__ Av,
                 const float* __restrict__ Bv,
                 const int* __restrict__ mask) {
    int bx = blockIdx.x;
    if (bx < XBLK) {
        int i = bx * 256 + threadIdx.x;
        g_xt[i] = rna_tf32(x[i]);
        return;
    }
    bx -= XBLK;
    if (bx < 2 * WBLK) {
        int i = bx * 256 + threadIdx.x;   // covers both Wk and Wo ranges
        if (bx < WBLK) g_wkt[i] = rna_tf32(Wk[i]);
        else           g_wot[i - WBLK * 256] = rna_tf32(Wo[i - WBLK * 256]);
        return;
    }
    bx -= 2 * WBLK;
    if (bx < 2 * WBLK) {
        const bool isQ = bx < WBLK;
        int idx = (isQ ? bx : bx - WBLK) * 256 + threadIdx.x;
        int j = idx / H, h = idx % H;
        const float* W  = isQ ? Wq : Wv;
        const float* A  = isQ ? Aq : Av;
        const float* Bm = isQ ? Bq : Bv;
        float acc = W[idx];
#pragma unroll
        for (int r = 0; r < 4; r++)
            acc = fmaf(SCALING * Bm[j * 4 + r], A[r * H + h], acc);
        (isQ ? g_weff_q : g_weff_v)[idx] = rna_tf32(acc);
        return;
    }
    bx -= 2 * WBLK;
    // mask compaction: one block per batch, warp 0 only
    if (threadIdx.x < 32) {
        int b = bx;
        int lane = threadIdx.x;
        int base = 0;
        for (int c = 0; c < T_ / 32; c++) {
            int key = c * 32 + lane;
            int v = (mask[b * T_ + key] != 0);
            unsigned bal = __ballot_sync(0xffffffffu, v);
            int pos = base + __popc(bal & ((1u << lane) - 1u));
            if (v) g_idx[b * T_ + pos] = key;
            base += __popc(bal);
        }
        if (lane == 0) g_vcnt[b] = base;
    }
}

// ============================================================
// tf32 GEMM (R4 config): C[n,j] = sum_h A[n,h]*W[j,h] + bias[j]
// Tile 128x128, BK=16, 2-stage cp.async, 256 thr (8 warps, 64x32).
// grid.x = 6*nsel, grid.y = 64.
// ============================================================
#define PITCH 20
#define NITER (H / 16)          // 48
#define STG_FLTS (128 * PITCH)  // 2560

__global__ __launch_bounds__(256)
void gemm_mma(const float* __restrict__ A,
              const float* W0, const float* W1, const float* W2,
              const float* b0, const float* b1, const float* b2,
              float* C0, float* C1, float* C2) {
    __shared__ float sA[2 * STG_FLTS];
    __shared__ float sW[2 * STG_FLTS];

    const int sel = blockIdx.x / 6;
    const float* W    = (sel == 0) ? W0 : (sel == 1) ? W1 : W2;
    const float* bias = (sel == 0) ? b0 : (sel == 1) ? b1 : b2;
    float*       C    = (sel == 0) ? C0 : (sel == 1) ? C1 : C2;

    const int tid  = threadIdx.x;
    const int wid  = tid >> 5;
    const int lane = tid & 31;
    const int lr   = lane >> 2;
    const int lc   = lane & 3;
    const int rowBase = blockIdx.y * 128;
    const int colBase = (blockIdx.x % 6) * 128;
    const int mwarp = (wid & 1) * 64;
    const int nwarp = (wid >> 1) * 32;

    const int e0 = tid,       row0 = e0 >> 2, c40 = (e0 & 3) << 2;
    const int e1 = tid + 256, row1 = e1 >> 2, c41 = (e1 & 3) << 2;
    const float* pA0 = A + (size_t)(rowBase + row0) * H + c40;
    const float* pA1 = A + (size_t)(rowBase + row1) * H + c41;
    const float* pW0 = W + (size_t)(colBase + row0) * H + c40;
    const float* pW1 = W + (size_t)(colBase + row1) * H + c41;
    const int s0 = row0 * PITCH + c40;
    const int s1 = row1 * PITCH + c41;

    const uint32_t aA = smem_u32(sA);
    const uint32_t aW = smem_u32(sW);

    float acc[4][4][4];
#pragma unroll
    for (int mt = 0; mt < 4; mt++)
#pragma unroll
        for (int nt = 0; nt < 4; nt++)
#pragma unroll
            for (int i = 0; i < 4; i++) acc[mt][nt][i] = 0.f;

    {
        cp_async16(aA + (uint32_t)(s0) * 4, pA0);
        cp_async16(aA + (uint32_t)(s1) * 4, pA1);
        cp_async16(aW + (uint32_t)(s0) * 4, pW0);
        cp_async16(aW + (uint32_t)(s1) * 4, pW1);
        CP_COMMIT();
    }

    for (int it = 0; it < NITER; it++) {
        if (it + 1 < NITER) {
            const int koff = (it + 1) * 16;
            const uint32_t stoff = (uint32_t)(((it + 1) & 1) * STG_FLTS) * 4;
            cp_async16(aA + stoff + (uint32_t)s0 * 4, pA0 + koff);
            cp_async16(aA + stoff + (uint32_t)s1 * 4, pA1 + koff);
            cp_async16(aW + stoff + (uint32_t)s0 * 4, pW0 + koff);
            cp_async16(aW + stoff + (uint32_t)s1 * 4, pW1 + koff);
            CP_COMMIT();
            CP_WAIT(1);
        } else {
            CP_WAIT(0);
        }
        __syncthreads();

        const float* cAf = sA + (it & 1) * STG_FLTS;
        const float* cWf = sW + (it & 1) * STG_FLTS;
#pragma unroll
        for (int ks = 0; ks < 2; ks++) {
            const int kb = ks * 8 + lc;
            float af[4][4], bf[4][2];
#pragma unroll
            for (int mt = 0; mt < 4; mt++) {
                const int m0 = mwarp + mt * 16 + lr;
                af[mt][0] = cAf[m0 * PITCH + kb];
                af[mt][1] = cAf[(m0 + 8) * PITCH + kb];
                af[mt][2] = cAf[m0 * PITCH + kb + 4];
                af[mt][3] = cAf[(m0 + 8) * PITCH + kb + 4];
            }
#pragma unroll
            for (int nt = 0; nt < 4; nt++) {
                const int n0 = nwarp + nt * 8 + lr;
                bf[nt][0] = cWf[n0 * PITCH + kb];
                bf[nt][1] = cWf[n0 * PITCH + kb + 4];
            }
#pragma unroll
            for (int mt = 0; mt < 4; mt++)
#pragma unroll
                for (int nt = 0; nt < 4; nt++)
                    mma_tf32f(acc[mt][nt], af[mt], bf[nt]);
        }
        __syncthreads();
    }

#pragma unroll
    for (int mt = 0; mt < 4; mt++) {
        const int r0 = rowBase + mwarp + mt * 16 + lr;
#pragma unroll
        for (int nt = 0; nt < 4; nt++) {
            const int c0 = colBase + nwarp + nt * 8 + lc * 2;
            const float bb0 = __ldg(&bias[c0]);
            const float bb1 = __ldg(&bias[c0 + 1]);
            float2 v0 = { acc[mt][nt][0] + bb0, acc[mt][nt][1] + bb1 };
            float2 v1 = { acc[mt][nt][2] + bb0, acc[mt][nt][3] + bb1 };
            *reinterpret_cast<float2*>(&C[(size_t)r0 * H + c0])       = v0;
            *reinterpret_cast<float2*>(&C[(size_t)(r0 + 8) * H + c0]) = v1;
        }
    }
}

// ============================================================
// Attention (R5 design): tensor-core S=QK^T and P*V, compacted
// keys, fp32 softmax + poly exp2. 128 thr (4 warps), 64 q-rows.
// grid = (8, 12, 16).
// ============================================================
#define QP 68
#define VP 72
#define ATT_SMEM ((64 * QP * 2 + 64 * VP) * 4 + T_ * 4)

extern __shared__ float asm_[];

__global__ __launch_bounds__(128)
void attn_kernel(const float* __restrict__ Q, const float* __restrict__ K,
                 const float* __restrict__ V, float* __restrict__ O) {
    float* sQ  = asm_;
    float* sKP = sQ + 64 * QP;
    float* sV  = sKP + 64 * QP;
    int*  sIdx = (int*)(sV + 64 * VP);

    const int qt = blockIdx.x;
    const int nh = blockIdx.y;
    const int b  = blockIdx.z;
    const int tid  = threadIdx.x;
    const int wid  = tid >> 5;
    const int lane = tid & 31;
    const int lr   = lane >> 2;
    const int lc   = lane & 3;
    const int qr   = wid * 16 + lr;

    const int vcnt = g_vcnt[b];
    for (int i = tid; i < T_; i += 128) sIdx[i] = g_idx[b * T_ + i];

    const float* Qb = Q + (size_t)(b * T_ + qt * 64) * H + nh * HD_;
    const float* Kb = K + (size_t)(b * T_) * H + nh * HD_;
    const float* Vb = V + (size_t)(b * T_) * H + nh * HD_;

#pragma unroll
    for (int it = 0; it < 16; it++) {
        int e = tid + it * 128;
        int row = e >> 5, c2 = (e & 31) << 1;
        float2 v = *reinterpret_cast<const float2*>(&Qb[row * H + c2]);
        float2 o = { rna_tf32(v.x * 0.125f), rna_tf32(v.y * 0.125f) };
        *reinterpret_cast<float2*>(&sQ[row * QP + c2]) = o;
    }
    __syncthreads();

    float aq[8][4];
#pragma unroll
    for (int ks = 0; ks < 8; ks++) {
        const int k0 = ks * 8;
        aq[ks][0] = sQ[qr * QP + k0 + lc];
        aq[ks][1] = sQ[(qr + 8) * QP + k0 + lc];
        aq[ks][2] = sQ[qr * QP + k0 + lc + 4];
        aq[ks][3] = sQ[(qr + 8) * QP + k0 + lc + 4];
    }

    float m0 = -1e30f, m1 = -1e30f, l0 = 0.f, l1 = 0.f;
    float accO[8][4];
#pragma unroll
    for (int nt = 0; nt < 8; nt++)
#pragma unroll
        for (int i = 0; i < 4; i++) accO[nt][i] = 0.f;

    const int ntiles = (vcnt + 63) >> 6;
    for (int kt = 0; kt < ntiles; kt++) {
        __syncthreads();
        const int base = kt << 6;
        const int nval = min(64, vcnt - base);

#pragma unroll
        for (int it = 0; it < 16; it++) {
            int e = tid + it * 128;
            int row = e >> 5, c2 = (e & 31) << 1;
            int grow = sIdx[base + ((row < nval) ? row : 0)];
            float2 kv = *reinterpret_cast<const float2*>(&Kb[(size_t)grow * H + c2]);
            float2 vv = *reinterpret_cast<const float2*>(&Vb[(size_t)grow * H + c2]);
            float2 ko = { rna_tf32(kv.x), rna_tf32(kv.y) };
            float2 vo = { rna_tf32(vv.x), rna_tf32(vv.y) };
            *reinterpret_cast<float2*>(&sKP[row * QP + c2]) = ko;
            *reinterpret_cast<float2*>(&sV[row * VP + c2])  = vo;
        }
        __syncthreads();

        float s[8][4];
#pragma unroll
        for (int nt = 0; nt < 8; nt++)
#pragma unroll
            for (int i = 0; i < 4; i++) s[nt][i] = 0.f;
#pragma unroll
        for (int nt = 0; nt < 8; nt++) {
            const int n0 = nt * 8 + lr;
#pragma unroll
            for (int ks = 0; ks < 8; ks++) {
                const int k0 = ks * 8;
                float bf[2];
                bf[0] = sKP[n0 * QP + k0 + lc];
                bf[1] = sKP[n0 * QP + k0 + lc + 4];
                mma_tf32f(s[nt], aq[ks], bf);
            }
        }

#pragma unroll
        for (int nt = 0; nt < 8; nt++) {
            const int c = nt * 8 + 2 * lc;
            if (c     >= nval) { s[nt][0] = -1e9f; s[nt][2] = -1e9f; }
            if (c + 1 >= nval) { s[nt][1] = -1e9f; s[nt][3] = -1e9f; }
        }

        float mx0 = s[0][0], mx1 = s[0][2];
#pragma unroll
        for (int nt = 0; nt < 8; nt++) {
            mx0 = fmaxf(mx0, fmaxf(s[nt][0], s[nt][1]));
            mx1 = fmaxf(mx1, fmaxf(s[nt][2], s[nt][3]));
        }
        mx0 = fmaxf(mx0, __shfl_xor_sync(0xffffffffu, mx0, 1));
        mx0 = fmaxf(mx0, __shfl_xor_sync(0xffffffffu, mx0, 2));
        mx1 = fmaxf(mx1, __shfl_xor_sync(0xffffffffu, mx1, 1));
        mx1 = fmaxf(mx1, __shfl_xor_sync(0xffffffffu, mx1, 2));

        float mn0 = fmaxf(m0, mx0), mn1 = fmaxf(m1, mx1);
        float cr0 = exp2p((m0 - mn0) * LOG2E);
        float cr1 = exp2p((m1 - mn1) * LOG2E);
        m0 = mn0; m1 = mn1;

        float ps0 = 0.f, ps1 = 0.f;
#pragma unroll
        for (int nt = 0; nt < 8; nt++) {
            s[nt][0] = exp2p((s[nt][0] - mn0) * LOG2E);
            s[nt][1] = exp2p((s[nt][1] - mn0) * LOG2E);
            s[nt][2] = exp2p((s[nt][2] - mn1) * LOG2E);
            s[nt][3] = exp2p((s[nt][3] - mn1) * LOG2E);
            ps0 += s[nt][0] + s[nt][1];
            ps1 += s[nt][2] + s[nt][3];
        }
        ps0 += __shfl_xor_sync(0xffffffffu, ps0, 1);
        ps0 += __shfl_xor_sync(0xffffffffu, ps0, 2);
        ps1 += __shfl_xor_sync(0xffffffffu, ps1, 1);
        ps1 += __shfl_xor_sync(0xffffffffu, ps1, 2);
        l0 = l0 * cr0 + ps0;
        l1 = l1 * cr1 + ps1;
#pragma unroll
        for (int nt = 0; nt < 8; nt++) {
            accO[nt][0] *= cr0; accO[nt][1] *= cr0;
            accO[nt][2] *= cr1; accO[nt][3] *= cr1;
        }

        __syncthreads();

#pragma unroll
        for (int nt = 0; nt < 8; nt++) {
            const int c = nt * 8 + 2 * lc;
            float2 p0 = { rna_tf32(s[nt][0]), rna_tf32(s[nt][1]) };
            float2 p1 = { rna_tf32(s[nt][2]), rna_tf32(s[nt][3]) };
            *reinterpret_cast<float2*>(&sKP[qr * QP + c])       = p0;
            *reinterpret_cast<float2*>(&sKP[(qr + 8) * QP + c]) = p1;
        }
        __syncwarp();

        float ap[8][4];
#pragma unroll
        for (int ks = 0; ks < 8; ks++) {
            const int k0 = ks * 8;
            ap[ks][0] = sKP[qr * QP + k0 + lc];
            ap[ks][1] = sKP[(qr + 8) * QP + k0 + lc];
            ap[ks][2] = sKP[qr * QP + k0 + lc + 4];
            ap[ks][3] = sKP[(qr + 8) * QP + k0 + lc + 4];
        }

#pragma unroll
        for (int nt = 0; nt < 8; nt++) {
            const int n0 = nt * 8 + lr;
#pragma unroll
            for (int ks = 0; ks < 8; ks++) {
                const int k0 = ks * 8;
                float bv[2];
                bv[0] = sV[(k0 + lc) * VP + n0];
                bv[1] = sV[(k0 + lc + 4) * VP + n0];
                mma_tf32f(accO[nt], ap[ks], bv);
            }
        }
    }

    float* Ob = O + (size_t)(b * T_ + qt * 64) * H + nh * HD_;
    const float i0 = 1.0f / l0, i1 = 1.0f / l1;
#pragma unroll
    for (int nt = 0; nt < 8; nt++) {
        const int c = nt * 8 + 2 * lc;
        float2 o0 = { rna_tf32(accO[nt][0] * i0), rna_tf32(accO[nt][1] * i0) };
        float2 o1 = { rna_tf32(accO[nt][2] * i1), rna_tf32(accO[nt][3] * i1) };
        *reinterpret_cast<float2*>(&Ob[qr * H + c])       = o0;
        *reinterpret_cast<float2*>(&Ob[(qr + 8) * H + c]) = o1;
    }
}

// ============================================================
// launch
// ============================================================
extern "C" void kernel_launch(void* const* d_in, const int* in_sizes, int n_in,
                              void* d_out, int out_size) {
    (void)in_sizes; (void)n_in; (void)out_size;
    const float* x  = (const float*)d_in[0];
    const int*  mask = (const int*) d_in[1];
    const float* Wq = (const float*)d_in[2];
    const float* bq = (const float*)d_in[3];
    const float* Aq = (const float*)d_in[4];
    const float* Bq = (const float*)d_in[5];
    const float* Wk = (const float*)d_in[6];
    const float* bk = (const float*)d_in[7];
    const float* Wv = (const float*)d_in[8];
    const float* bv = (const float*)d_in[9];
    const float* Av = (const float*)d_in[10];
    const float* Bv = (const float*)d_in[11];
    const float* Wo = (const float*)d_in[12];
    const float* bo = (const float*)d_in[13];
    float* out = (float*)d_out;

    float *pxt, *pweff_q, *pweff_v, *pwkt, *pwot, *pq, *pk, *pv, *pao;
    cudaGetSymbolAddress((void**)&pxt, g_xt);
    cudaGetSymbolAddress((void**)&pweff_q, g_weff_q);
    cudaGetSymbolAddress((void**)&pweff_v, g_weff_v);
    cudaGetSymbolAddress((void**)&pwkt, g_wkt);
    cudaGetSymbolAddress((void**)&pwot, g_wot);
    cudaGetSymbolAddress((void**)&pq, g_q);
    cudaGetSymbolAddress((void**)&pk, g_k);
    cudaGetSymbolAddress((void**)&pv, g_v);
    cudaGetSymbolAddress((void**)&pao, g_ao);

    static bool attr_set = false;
    if (!attr_set) {
        cudaFuncSetAttribute(attn_kernel,
            cudaFuncAttributeMaxDynamicSharedMemorySize, ATT_SMEM);
        attr_set = true;
    }

    // fused prep (cvt x/Wk/Wo, weff q/v, compaction)
    prep_kernel<<<XBLK + 4 * WBLK + B_, 256>>>(
        x, Wk, Wo, Wq, Aq, Bq, Wv, Av, Bv, mask);

    // fused Q/K/V projection
    gemm_mma<<<dim3(18, NROWS / 128), 256>>>(
        pxt, pweff_q, pwkt, pweff_v, bq, bk, bv, pq, pk, pv);

    // attention
    attn_kernel<<<dim3(T_ / 64, NH_, B_), 128, ATT_SMEM>>>(pq, pk, pv, pao);

    // output projection
    gemm_mma<<<dim3(6, NROWS / 128), 256>>>(
        pao, pwot, pwot, pwot, bo, bo, bo, out, out, out);
}

// round 7
// speedup vs baseline: 1.7910x; 1.1739x over previous
#include <cuda_runtime.h>
#include <cstdint>

#define H   768
#define NH_ 12
#define HD_ 64
#define B_  16
#define T_  512
#define NROWS (B_ * T_)
#define SCALING 2.0f

// -------- device scratch --------
__device__ float g_xt  [(size_t)NROWS * H];
__device__ float g_weff_q[H * H];
__device__ float g_weff_v[H * H];
__device__ float g_wkt [H * H];
__device__ float g_wot [H * H];
__device__ float g_q [(size_t)NROWS * H];
__device__ float g_k [(size_t)NROWS * H];
__device__ float g_v [(size_t)NROWS * H];
__device__ float g_ao[(size_t)NROWS * H];
__device__ int   g_idx[B_ * T_];
__device__ int   g_vcnt[B_];

// ============================================================
// helpers
// ============================================================
__device__ __forceinline__ float rna_tf32(float x) {
    uint32_t u;
    asm("cvt.rna.tf32.f32 %0, %1;" : "=r"(u) : "f"(x));
    return __uint_as_float(u);
}

// d fp32 accum; a,b are tf32 bit-pattern fragments
__device__ __forceinline__ void mma_u(float* d, const uint32_t* a,
                                      uint32_t b0, uint32_t b1) {
    asm volatile(
        "mma.sync.aligned.m16n8k8.row.col.f32.tf32.tf32.f32 "
        "{%0,%1,%2,%3}, {%4,%5,%6,%7}, {%8,%9}, {%0,%1,%2,%3};"
        : "+f"(d[0]), "+f"(d[1]), "+f"(d[2]), "+f"(d[3])
        : "r"(a[0]), "r"(a[1]), "r"(a[2]), "r"(a[3]), "r"(b0), "r"(b1));
}

__device__ __forceinline__ uint32_t smem_u32(const void* p) {
    uint32_t a;
    asm("{ .reg .u64 t; cvta.to.shared.u64 t, %1; cvt.u32.u64 %0, t; }"
        : "=r"(a) : "l"(p));
    return a;
}

#define LDSM_X4(d0, d1, d2, d3, addr)                                        \
    asm volatile("ldmatrix.sync.aligned.m8n8.x4.shared.b16 {%0,%1,%2,%3}, [%4];" \
        : "=r"(d0), "=r"(d1), "=r"(d2), "=r"(d3) : "r"(addr))

__device__ __forceinline__ void cp_async16(uint32_t dst, const void* src) {
    asm volatile("cp.async.ca.shared.global [%0], [%1], 16;" :: "r"(dst), "l"(src));
}
#define CP_COMMIT() asm volatile("cp.async.commit_group;" ::: "memory")
#define CP_WAIT(n)  asm volatile("cp.async.wait_group %0;" :: "n"(n) : "memory")

// polynomial 2^t for t <= 0 (FMA pipe). rel err ~1e-5.
__device__ __forceinline__ float exp2p(float t) {
    t = fmaxf(t, -126.f);
    float fi = floorf(t);
    float f  = t - fi;
    float p  = 0.0001540353f;
    p = fmaf(p, f, 0.0013333558f);
    p = fmaf(p, f, 0.0096181291f);
    p = fmaf(p, f, 0.0555041087f);
    p = fmaf(p, f, 0.2402265070f);
    p = fmaf(p, f, 0.6931471806f);
    p = fmaf(p, f, 1.0f);
    int ei = (int)fi;
    return p * __int_as_float((ei + 127) << 23);
}
#define LOG2E 1.4426950408889634f

// ============================================================
// fused prep: cvt x/Wk/Wo, weff q/v, mask compaction — 1 launch
// ============================================================
#define XBLK  (NROWS * H / 256)   // 24576
#define WBLK  (H * H / 256)       // 2304

__global__ __launch_bounds__(256)
void prep_kernel(const float* __restrict__ x,
                 const float* __restrict__ Wk, const float* __restrict__ Wo,
                 const float* __restrict__ Wq, const float* __restrict__ Aq,
                 const float* __restrict__ Bq,
                 const float* __restrict__ Wv, const float* __restrict__ Av,
                 const float* __restrict__ Bv,
                 const int* __restrict__ mask) {
    int bx = blockIdx.x;
    if (bx < XBLK) {
        int i = bx * 256 + threadIdx.x;
        g_xt[i] = rna_tf32(x[i]);
        return;
    }
    bx -= XBLK;
    if (bx < 2 * WBLK) {
        int i = bx * 256 + threadIdx.x;
        if (bx < WBLK) g_wkt[i] = rna_tf32(Wk[i]);
        else           g_wot[i - WBLK * 256] = rna_tf32(Wo[i - WBLK * 256]);
        return;
    }
    bx -= 2 * WBLK;
    if (bx < 2 * WBLK) {
        const bool isQ = bx < WBLK;
        int idx = (isQ ? bx : bx - WBLK) * 256 + threadIdx.x;
        int j = idx / H, h = idx % H;
        const float* W  = isQ ? Wq : Wv;
        const float* A  = isQ ? Aq : Av;
        const float* Bm = isQ ? Bq : Bv;
        float acc = W[idx];
#pragma unroll
        for (int r = 0; r < 4; r++)
            acc = fmaf(SCALING * Bm[j * 4 + r], A[r * H + h], acc);
        (isQ ? g_weff_q : g_weff_v)[idx] = rna_tf32(acc);
        return;
    }
    bx -= 2 * WBLK;
    if (threadIdx.x < 32) {
        int b = bx;
        int lane = threadIdx.x;
        int base = 0;
        for (int c = 0; c < T_ / 32; c++) {
            int key = c * 32 + lane;
            int v = (mask[b * T_ + key] != 0);
            unsigned bal = __ballot_sync(0xffffffffu, v);
            int pos = base + __popc(bal & ((1u << lane) - 1u));
            if (v) g_idx[b * T_ + pos] = key;
            base += __popc(bal);
        }
        if (lane == 0) g_vcnt[b] = base;
    }
}

// ============================================================
// tf32 GEMM, ldmatrix fragments, 3-stage cp.async, 1 sync/iter.
// C[n,j] = sum_h A[n,h]*W[j,h] + bias[j]
// Tile 128x128, BK=16, 256 thr (8 warps, 64x32 each).
// ============================================================
#define PITCH 20
#define NITER (H / 16)            // 48
#define STG_FLTS (128 * PITCH)    // 2560 floats (one operand, one stage)
#define STAGE_FLTS (2 * STG_FLTS) // A + W
#define GEMM_SMEM (3 * STAGE_FLTS * 4)   // 61440 B

extern __shared__ float gsm[];

__global__ __launch_bounds__(256, 2)
void gemm_mma(const float* __restrict__ A,
              const float* W0, const float* W1, const float* W2,
              const float* b0, const float* b1, const float* b2,
              float* C0, float* C1, float* C2) {
    const int sel = blockIdx.x / 6;
    const float* W    = (sel == 0) ? W0 : (sel == 1) ? W1 : W2;
    const float* bias = (sel == 0) ? b0 : (sel == 1) ? b1 : b2;
    float*       C    = (sel == 0) ? C0 : (sel == 1) ? C1 : C2;

    const int tid  = threadIdx.x;
    const int wid  = tid >> 5;
    const int lane = tid & 31;
    const int lr   = lane >> 2;
    const int lc   = lane & 3;
    const int rowBase = blockIdx.y * 128;
    const int colBase = (blockIdx.x % 6) * 128;
    const int mwarp = (wid & 1) * 64;
    const int nwarp = (wid >> 1) * 32;

    const uint32_t sb = smem_u32(gsm);

    // cp.async slots (2 for A, 2 for W per thread per stage)
    const int e0 = tid,       row0 = e0 >> 2, c40 = (e0 & 3) << 2;
    const int e1 = tid + 256, row1 = e1 >> 2, c41 = (e1 & 3) << 2;
    const float* pA0 = A + (size_t)(rowBase + row0) * H + c40;
    const float* pA1 = A + (size_t)(rowBase + row1) * H + c41;
    const float* pW0 = W + (size_t)(colBase + row0) * H + c40;
    const float* pW1 = W + (size_t)(colBase + row1) * H + c41;
    const uint32_t s0 = (uint32_t)(row0 * PITCH + c40) * 4;
    const uint32_t s1 = (uint32_t)(row1 * PITCH + c41) * 4;

    // ldmatrix per-thread row offsets (floats)
    const int rpA = (lane & 15) * PITCH + ((lane >> 4) << 2);
    const int rpB = ((lane & 7) + ((lane & 16) >> 1)) * PITCH + ((lane & 8) >> 1);

    float acc[4][4][4];
#pragma unroll
    for (int mt = 0; mt < 4; mt++)
#pragma unroll
        for (int nt = 0; nt < 4; nt++)
#pragma unroll
            for (int i = 0; i < 4; i++) acc[mt][nt][i] = 0.f;

    auto load_stage = [&](int it, int st) {
        const int koff = it * 16;
        const uint32_t base = sb + (uint32_t)(st * STAGE_FLTS) * 4;
        cp_async16(base + s0, pA0 + koff);
        cp_async16(base + s1, pA1 + koff);
        cp_async16(base + (uint32_t)STG_FLTS * 4 + s0, pW0 + koff);
        cp_async16(base + (uint32_t)STG_FLTS * 4 + s1, pW1 + koff);
        CP_COMMIT();
    };

    load_stage(0, 0);
    load_stage(1, 1);

    for (int it = 0; it < NITER; it++) {
        if (it + 1 < NITER) { CP_WAIT(1); } else { CP_WAIT(0); }
        __syncthreads();
        if (it + 2 < NITER) load_stage(it + 2, (it + 2) % 3);

        const uint32_t stA = sb + (uint32_t)((it % 3) * STAGE_FLTS) * 4;
        const uint32_t stW = stA + (uint32_t)STG_FLTS * 4;
#pragma unroll
        for (int ks = 0; ks < 2; ks++) {
            uint32_t af[4][4], bf[4][2];
#pragma unroll
            for (int mt = 0; mt < 4; mt++)
                LDSM_X4(af[mt][0], af[mt][1], af[mt][2], af[mt][3],
                        stA + (uint32_t)((mwarp + mt * 16) * PITCH + ks * 8 + rpA) * 4);
#pragma unroll
            for (int ntp = 0; ntp < 2; ntp++)
                LDSM_X4(bf[2 * ntp][0], bf[2 * ntp][1], bf[2 * ntp + 1][0], bf[2 * ntp + 1][1],
                        stW + (uint32_t)((nwarp + ntp * 16) * PITCH + ks * 8 + rpB) * 4);
#pragma unroll
            for (int mt = 0; mt < 4; mt++)
#pragma unroll
                for (int nt = 0; nt < 4; nt++)
                    mma_u(acc[mt][nt], af[mt], bf[nt][0], bf[nt][1]);
        }
    }

#pragma unroll
    for (int mt = 0; mt < 4; mt++) {
        const int r0 = rowBase + mwarp + mt * 16 + lr;
#pragma unroll
        for (int nt = 0; nt < 4; nt++) {
            const int c0 = colBase + nwarp + nt * 8 + lc * 2;
            const float bb0 = __ldg(&bias[c0]);
            const float bb1 = __ldg(&bias[c0 + 1]);
            float2 v0 = { acc[mt][nt][0] + bb0, acc[mt][nt][1] + bb1 };
            float2 v1 = { acc[mt][nt][2] + bb0, acc[mt][nt][3] + bb1 };
            *reinterpret_cast<float2*>(&C[(size_t)r0 * H + c0])       = v0;
            *reinterpret_cast<float2*>(&C[(size_t)(r0 + 8) * H + c0]) = v1;
        }
    }
}

// ============================================================
// Attention: tensor-core S=QK^T and P*V, ldmatrix for Q/K/P
// fragments, compacted keys, fp32 softmax + poly exp2.
// 128 thr (4 warps), 64 q-rows/block. grid = (8, 12, 16).
// ============================================================
#define QP 68
#define VP 72
#define ATT_SMEM ((64 * QP * 2 + 64 * VP) * 4 + T_ * 4)

extern __shared__ float asm_[];

__global__ __launch_bounds__(128)
void attn_kernel(const float* __restrict__ Q, const float* __restrict__ K,
                 const float* __restrict__ V, float* __restrict__ O) {
    float* sQ  = asm_;
    float* sKP = sQ + 64 * QP;
    float* sV  = sKP + 64 * QP;
    int*  sIdx = (int*)(sV + 64 * VP);

    const int qt = blockIdx.x;
    const int nh = blockIdx.y;
    const int b  = blockIdx.z;
    const int tid  = threadIdx.x;
    const int wid  = tid >> 5;
    const int lane = tid & 31;
    const int lr   = lane >> 2;
    const int lc   = lane & 3;
    const int qr   = wid * 16 + lr;

    const uint32_t aQ  = smem_u32(sQ);
    const uint32_t aKP = smem_u32(sKP);
    const int rpA = (lane & 15) * QP + ((lane >> 4) << 2);
    const int rpB = ((lane & 7) + ((lane & 16) >> 1)) * QP + ((lane & 8) >> 1);

    const int vcnt = g_vcnt[b];
    for (int i = tid; i < T_; i += 128) sIdx[i] = g_idx[b * T_ + i];

    const float* Qb = Q + (size_t)(b * T_ + qt * 64) * H + nh * HD_;
    const float* Kb = K + (size_t)(b * T_) * H + nh * HD_;
    const float* Vb = V + (size_t)(b * T_) * H + nh * HD_;

#pragma unroll
    for (int it = 0; it < 16; it++) {
        int e = tid + it * 128;
        int row = e >> 5, c2 = (e & 31) << 1;
        float2 v = *reinterpret_cast<const float2*>(&Qb[row * H + c2]);
        float2 o = { rna_tf32(v.x * 0.125f), rna_tf32(v.y * 0.125f) };
        *reinterpret_cast<float2*>(&sQ[row * QP + c2]) = o;
    }
    __syncthreads();

    uint32_t aq[8][4];
#pragma unroll
    for (int ks = 0; ks < 8; ks++)
        LDSM_X4(aq[ks][0], aq[ks][1], aq[ks][2], aq[ks][3],
                aQ + (uint32_t)(wid * 16 * QP + ks * 8 + rpA) * 4);

    float m0 = -1e30f, m1 = -1e30f, l0 = 0.f, l1 = 0.f;
    float accO[8][4];
#pragma unroll
    for (int nt = 0; nt < 8; nt++)
#pragma unroll
        for (int i = 0; i < 4; i++) accO[nt][i] = 0.f;

    const int ntiles = (vcnt + 63) >> 6;
    for (int kt = 0; kt < ntiles; kt++) {
        __syncthreads();
        const int base = kt << 6;
        const int nval = min(64, vcnt - base);

#pragma unroll
        for (int it = 0; it < 16; it++) {
            int e = tid + it * 128;
            int row = e >> 5, c2 = (e & 31) << 1;
            int grow = sIdx[base + ((row < nval) ? row : 0)];
            float2 kv = *reinterpret_cast<const float2*>(&Kb[(size_t)grow * H + c2]);
            float2 vv = *reinterpret_cast<const float2*>(&Vb[(size_t)grow * H + c2]);
            float2 ko = { rna_tf32(kv.x), rna_tf32(kv.y) };
            float2 vo = { rna_tf32(vv.x), rna_tf32(vv.y) };
            *reinterpret_cast<float2*>(&sKP[row * QP + c2]) = ko;
            *reinterpret_cast<float2*>(&sV[row * VP + c2])  = vo;
        }
        __syncthreads();

        // S = Q K^T with ldmatrix B-fragments
        float s[8][4];
#pragma unroll
        for (int nt = 0; nt < 8; nt++)
#pragma unroll
            for (int i = 0; i < 4; i++) s[nt][i] = 0.f;
#pragma unroll
        for (int ks = 0; ks < 8; ks++) {
#pragma unroll
            for (int ntp = 0; ntp < 4; ntp++) {
                uint32_t b00, b01, b10, b11;
                LDSM_X4(b00, b01, b10, b11,
                        aKP + (uint32_t)(ntp * 16 * QP + ks * 8 + rpB) * 4);
                mma_u(s[2 * ntp],     aq[ks], b00, b01);
                mma_u(s[2 * ntp + 1], aq[ks], b10, b11);
            }
        }

#pragma unroll
        for (int nt = 0; nt < 8; nt++) {
            const int c = nt * 8 + 2 * lc;
            if (c     >= nval) { s[nt][0] = -1e9f; s[nt][2] = -1e9f; }
            if (c + 1 >= nval) { s[nt][1] = -1e9f; s[nt][3] = -1e9f; }
        }

        float mx0 = s[0][0], mx1 = s[0][2];
#pragma unroll
        for (int nt = 0; nt < 8; nt++) {
            mx0 = fmaxf(mx0, fmaxf(s[nt][0], s[nt][1]));
            mx1 = fmaxf(mx1, fmaxf(s[nt][2], s[nt][3]));
        }
        mx0 = fmaxf(mx0, __shfl_xor_sync(0xffffffffu, mx0, 1));
        mx0 = fmaxf(mx0, __shfl_xor_sync(0xffffffffu, mx0, 2));
        mx1 = fmaxf(mx1, __shfl_xor_sync(0xffffffffu, mx1, 1));
        mx1 = fmaxf(mx1, __shfl_xor_sync(0xffffffffu, mx1, 2));

        float mn0 = fmaxf(m0, mx0), mn1 = fmaxf(m1, mx1);
        float cr0 = exp2p((m0 - mn0) * LOG2E);
        float cr1 = exp2p((m1 - mn1) * LOG2E);
        m0 = mn0; m1 = mn1;

        float ps0 = 0.f, ps1 = 0.f;
#pragma unroll
        for (int nt = 0; nt < 8; nt++) {
            s[nt][0] = exp2p((s[nt][0] - mn0) * LOG2E);
            s[nt][1] = exp2p((s[nt][1] - mn0) * LOG2E);
            s[nt][2] = exp2p((s[nt][2] - mn1) * LOG2E);
            s[nt][3] = exp2p((s[nt][3] - mn1) * LOG2E);
            ps0 += s[nt][0] + s[nt][1];
            ps1 += s[nt][2] + s[nt][3];
        }
        ps0 += __shfl_xor_sync(0xffffffffu, ps0, 1);
        ps0 += __shfl_xor_sync(0xffffffffu, ps0, 2);
        ps1 += __shfl_xor_sync(0xffffffffu, ps1, 1);
        ps1 += __shfl_xor_sync(0xffffffffu, ps1, 2);
        l0 = l0 * cr0 + ps0;
        l1 = l1 * cr1 + ps1;
#pragma unroll
        for (int nt = 0; nt < 8; nt++) {
            accO[nt][0] *= cr0; accO[nt][1] *= cr0;
            accO[nt][2] *= cr1; accO[nt][3] *= cr1;
        }

        __syncthreads();   // all warps done reading sKP as K

        // store P (rna) into own 16 rows, reload as ldmatrix A-fragments
#pragma unroll
        for (int nt = 0; nt < 8; nt++) {
            const int c = nt * 8 + 2 * lc;
            float2 p0 = { rna_tf32(s[nt][0]), rna_tf32(s[nt][1]) };
            float2 p1 = { rna_tf32(s[nt][2]), rna_tf32(s[nt][3]) };
            *reinterpret_cast<float2*>(&sKP[qr * QP + c])       = p0;
            *reinterpret_cast<float2*>(&sKP[(qr + 8) * QP + c]) = p1;
        }
        __syncwarp();

        uint32_t ap[8][4];
#pragma unroll
        for (int ks = 0; ks < 8; ks++)
            LDSM_X4(ap[ks][0], ap[ks][1], ap[ks][2], ap[ks][3],
                    aKP + (uint32_t)(wid * 16 * QP + ks * 8 + rpA) * 4);

        // O += P * V  (V fragments via scalar LDS, layout [key][d])
#pragma unroll
        for (int nt = 0; nt < 8; nt++) {
            const int n0 = nt * 8 + lr;
#pragma unroll
            for (int ks = 0; ks < 8; ks++) {
                const int k0 = ks * 8;
                uint32_t bv0 = __float_as_uint(sV[(k0 + lc) * VP + n0]);
                uint32_t bv1 = __float_as_uint(sV[(k0 + lc + 4) * VP + n0]);
                mma_u(accO[nt], ap[ks], bv0, bv1);
            }
        }
    }

    float* Ob = O + (size_t)(b * T_ + qt * 64) * H + nh * HD_;
    const float i0 = 1.0f / l0, i1 = 1.0f / l1;
#pragma unroll
    for (int nt = 0; nt < 8; nt++) {
        const int c = nt * 8 + 2 * lc;
        float2 o0 = { rna_tf32(accO[nt][0] * i0), rna_tf32(accO[nt][1] * i0) };
        float2 o1 = { rna_tf32(accO[nt][2] * i1), rna_tf32(accO[nt][3] * i1) };
        *reinterpret_cast<float2*>(&Ob[qr * H + c])       = o0;
        *reinterpret_cast<float2*>(&Ob[(qr + 8) * H + c]) = o1;
    }
}

// ============================================================
// launch
// ============================================================
extern "C" void kernel_launch(void* const* d_in, const int* in_sizes, int n_in,
                              void* d_out, int out_size) {
    (void)in_sizes; (void)n_in; (void)out_size;
    const float* x  = (const float*)d_in[0];
    const int*  mask = (const int*) d_in[1];
    const float* Wq = (const float*)d_in[2];
    const float* bq = (const float*)d_in[3];
    const float* Aq = (const float*)d_in[4];
    const float* Bq = (const float*)d_in[5];
    const float* Wk = (const float*)d_in[6];
    const float* bk = (const float*)d_in[7];
    const float* Wv = (const float*)d_in[8];
    const float* bv = (const float*)d_in[9];
    const float* Av = (const float*)d_in[10];
    const float* Bv = (const float*)d_in[11];
    const float* Wo = (const float*)d_in[12];
    const float* bo = (const float*)d_in[13];
    float* out = (float*)d_out;

    float *pxt, *pweff_q, *pweff_v, *pwkt, *pwot, *pq, *pk, *pv, *pao;
    cudaGetSymbolAddress((void**)&pxt, g_xt);
    cudaGetSymbolAddress((void**)&pweff_q, g_weff_q);
    cudaGetSymbolAddress((void**)&pweff_v, g_weff_v);
    cudaGetSymbolAddress((void**)&pwkt, g_wkt);
    cudaGetSymbolAddress((void**)&pwot, g_wot);
    cudaGetSymbolAddress((void**)&pq, g_q);
    cudaGetSymbolAddress((void**)&pk, g_k);
    cudaGetSymbolAddress((void**)&pv, g_v);
    cudaGetSymbolAddress((void**)&pao, g_ao);

    static bool attr_set = false;
    if (!attr_set) {
        cudaFuncSetAttribute(gemm_mma,
            cudaFuncAttributeMaxDynamicSharedMemorySize, GEMM_SMEM);
        cudaFuncSetAttribute(attn_kernel,
            cudaFuncAttributeMaxDynamicSharedMemorySize, ATT_SMEM);
        attr_set = true;
    }

    prep_kernel<<<XBLK + 4 * WBLK + B_, 256>>>(
        x, Wk, Wo, Wq, Aq, Bq, Wv, Av, Bv, mask);

    gemm_mma<<<dim3(18, NROWS / 128), 256, GEMM_SMEM>>>(
        pxt, pweff_q, pwkt, pweff_v, bq, bk, bv, pq, pk, pv);

    attn_kernel<<<dim3(T_ / 64, NH_, B_), 128, ATT_SMEM>>>(pq, pk, pv, pao);

    gemm_mma<<<dim3(6, NROWS / 128), 256, GEMM_SMEM>>>(
        pao, pwot, pwot, pwot, bo, bo, bo, out, out, out);
}

// round 8
// speedup vs baseline: 1.9736x; 1.1019x over previous
#include <cuda_runtime.h>
#include <cstdint>

#define H   768
#define NH_ 12
#define HD_ 64
#define B_  16
#define T_  512
#define NROWS (B_ * T_)
#define SCALING 2.0f

// -------- device scratch --------
__device__ float g_xt  [(size_t)NROWS * H];
__device__ float g_weff_q[H * H];
__device__ float g_weff_v[H * H];
__device__ float g_wkt [H * H];
__device__ float g_wot [H * H];
__device__ float g_q [(size_t)NROWS * H];
__device__ float g_k [(size_t)NROWS * H];
__device__ float g_v [(size_t)NROWS * H];
__device__ float g_ao[(size_t)NROWS * H];
__device__ int   g_idx[B_ * T_];
__device__ int   g_vcnt[B_];

// ============================================================
// helpers
// ============================================================
__device__ __forceinline__ float rna_tf32(float x) {
    uint32_t u;
    asm("cvt.rna.tf32.f32 %0, %1;" : "=r"(u) : "f"(x));
    return __uint_as_float(u);
}

__device__ __forceinline__ void mma_u(float* d, const uint32_t* a,
                                      uint32_t b0, uint32_t b1) {
    asm volatile(
        "mma.sync.aligned.m16n8k8.row.col.f32.tf32.tf32.f32 "
        "{%0,%1,%2,%3}, {%4,%5,%6,%7}, {%8,%9}, {%0,%1,%2,%3};"
        : "+f"(d[0]), "+f"(d[1]), "+f"(d[2]), "+f"(d[3])
        : "r"(a[0]), "r"(a[1]), "r"(a[2]), "r"(a[3]), "r"(b0), "r"(b1));
}

__device__ __forceinline__ uint32_t smem_u32(const void* p) {
    uint32_t a;
    asm("{ .reg .u64 t; cvta.to.shared.u64 t, %1; cvt.u32.u64 %0, t; }"
        : "=r"(a) : "l"(p));
    return a;
}

#define LDSM_X4(d0, d1, d2, d3, addr)                                        \
    asm volatile("ldmatrix.sync.aligned.m8n8.x4.shared.b16 {%0,%1,%2,%3}, [%4];" \
        : "=r"(d0), "=r"(d1), "=r"(d2), "=r"(d3) : "r"(addr))

__device__ __forceinline__ void cp_async16(uint32_t dst, const void* src) {
    asm volatile("cp.async.ca.shared.global [%0], [%1], 16;" :: "r"(dst), "l"(src));
}
#define CP_COMMIT() asm volatile("cp.async.commit_group;" ::: "memory")
#define CP_WAIT(n)  asm volatile("cp.async.wait_group %0;" :: "n"(n) : "memory")

// polynomial 2^t for t <= 0 (FMA pipe). rel err ~1e-5.
__device__ __forceinline__ float exp2p(float t) {
    t = fmaxf(t, -126.f);
    float fi = floorf(t);
    float f  = t - fi;
    float p  = 0.0001540353f;
    p = fmaf(p, f, 0.0013333558f);
    p = fmaf(p, f, 0.0096181291f);
    p = fmaf(p, f, 0.0555041087f);
    p = fmaf(p, f, 0.2402265070f);
    p = fmaf(p, f, 0.6931471806f);
    p = fmaf(p, f, 1.0f);
    int ei = (int)fi;
    return p * __int_as_float((ei + 127) << 23);
}
#define LOG2E 1.4426950408889634f

// ============================================================
// fused prep: cvt x/Wk/Wo, weff q/v, mask compaction — 1 launch
// ============================================================
#define XBLK  (NROWS * H / 256)   // 24576
#define WBLK  (H * H / 256)       // 2304

__global__ __launch_bounds__(256)
void prep_kernel(const float* __restrict__ x,
                 const float* __restrict__ Wk, const float* __restrict__ Wo,
                 const float* __restrict__ Wq, const float* __restrict__ Aq,
                 const float* __restrict__ Bq,
                 const float* __restrict__ Wv, const float* __restrict__ Av,
                 const float* __restrict__ Bv,
                 const int* __restrict__ mask) {
    int bx = blockIdx.x;
    if (bx < XBLK) {
        int i = bx * 256 + threadIdx.x;
        g_xt[i] = rna_tf32(x[i]);
        return;
    }
    bx -= XBLK;
    if (bx < 2 * WBLK) {
        int i = bx * 256 + threadIdx.x;
        if (bx < WBLK) g_wkt[i] = rna_tf32(Wk[i]);
        else           g_wot[i - WBLK * 256] = rna_tf32(Wo[i - WBLK * 256]);
        return;
    }
    bx -= 2 * WBLK;
    if (bx < 2 * WBLK) {
        const bool isQ = bx < WBLK;
        int idx = (isQ ? bx : bx - WBLK) * 256 + threadIdx.x;
        int j = idx / H, h = idx % H;
        const float* W  = isQ ? Wq : Wv;
        const float* A  = isQ ? Aq : Av;
        const float* Bm = isQ ? Bq : Bv;
        float acc = W[idx];
#pragma unroll
        for (int r = 0; r < 4; r++)
            acc = fmaf(SCALING * Bm[j * 4 + r], A[r * H + h], acc);
        (isQ ? g_weff_q : g_weff_v)[idx] = rna_tf32(acc);
        return;
    }
    bx -= 2 * WBLK;
    if (threadIdx.x < 32) {
        int b = bx;
        int lane = threadIdx.x;
        int base = 0;
        for (int c = 0; c < T_ / 32; c++) {
            int key = c * 32 + lane;
            int v = (mask[b * T_ + key] != 0);
            unsigned bal = __ballot_sync(0xffffffffu, v);
            int pos = base + __popc(bal & ((1u << lane) - 1u));
            if (v) g_idx[b * T_ + pos] = key;
            base += __popc(bal);
        }
        if (lane == 0) g_vcnt[b] = base;
    }
}

// ============================================================
// tf32 GEMM: 128x128 CTA tile, 4 warps @ 64x64 each, BK=16,
// ldmatrix fragments, 3-stage cp.async, 1 sync/iter, 128 thr.
// C[n,j] = sum_h A[n,h]*W[j,h] + bias[j]
// ============================================================
#define PITCH 20
#define NITER (H / 16)            // 48
#define STG_FLTS (128 * PITCH)    // 2560 floats (one operand, one stage)
#define STAGE_FLTS (2 * STG_FLTS) // A + W
#define GEMM_SMEM (3 * STAGE_FLTS * 4)   // 61440 B

extern __shared__ float gsm[];

__global__ __launch_bounds__(128, 1)
void gemm_mma(const float* __restrict__ A,
              const float* W0, const float* W1, const float* W2,
              const float* b0, const float* b1, const float* b2,
              float* C0, float* C1, float* C2) {
    const int sel = blockIdx.x / 6;
    const float* W    = (sel == 0) ? W0 : (sel == 1) ? W1 : W2;
    const float* bias = (sel == 0) ? b0 : (sel == 1) ? b1 : b2;
    float*       C    = (sel == 0) ? C0 : (sel == 1) ? C1 : C2;

    const int tid  = threadIdx.x;
    const int wid  = tid >> 5;
    const int lane = tid & 31;
    const int lr   = lane >> 2;
    const int lc   = lane & 3;
    const int rowBase = blockIdx.y * 128;
    const int colBase = (blockIdx.x % 6) * 128;
    const int mwarp = (wid & 1) * 64;
    const int nwarp = (wid >> 1) * 64;

    const uint32_t sb = smem_u32(gsm);

    // cp.async slots: 4 for A, 4 for W per thread per stage
    int rowi[4], c4i[4];
#pragma unroll
    for (int i = 0; i < 4; i++) {
        int e = tid + i * 128;
        rowi[i] = e >> 2;
        c4i[i]  = (e & 3) << 2;
    }

    // ldmatrix per-thread row offsets (floats)
    const int rpA = (lane & 15) * PITCH + ((lane >> 4) << 2);
    const int rpB = ((lane & 7) + ((lane & 16) >> 1)) * PITCH + ((lane & 8) >> 1);

    float acc[4][8][4];
#pragma unroll
    for (int mt = 0; mt < 4; mt++)
#pragma unroll
        for (int nt = 0; nt < 8; nt++)
#pragma unroll
            for (int i = 0; i < 4; i++) acc[mt][nt][i] = 0.f;

    auto load_stage = [&](int it, int st) {
        const int koff = it * 16;
        const uint32_t base = sb + (uint32_t)(st * STAGE_FLTS) * 4;
#pragma unroll
        for (int i = 0; i < 4; i++) {
            cp_async16(base + (uint32_t)(rowi[i] * PITCH + c4i[i]) * 4,
                       A + (size_t)(rowBase + rowi[i]) * H + koff + c4i[i]);
            cp_async16(base + (uint32_t)(STG_FLTS + rowi[i] * PITCH + c4i[i]) * 4,
                       W + (size_t)(colBase + rowi[i]) * H + koff + c4i[i]);
        }
        CP_COMMIT();
    };

    load_stage(0, 0);
    load_stage(1, 1);

    for (int it = 0; it < NITER; it++) {
        if (it + 1 < NITER) { CP_WAIT(1); } else { CP_WAIT(0); }
        __syncthreads();
        if (it + 2 < NITER) load_stage(it + 2, (it + 2) % 3);

        const uint32_t stA = sb + (uint32_t)((it % 3) * STAGE_FLTS) * 4;
        const uint32_t stW = stA + (uint32_t)STG_FLTS * 4;
#pragma unroll
        for (int ks = 0; ks < 2; ks++) {
            uint32_t af[4][4], bf[8][2];
#pragma unroll
            for (int mt = 0; mt < 4; mt++)
                LDSM_X4(af[mt][0], af[mt][1], af[mt][2], af[mt][3],
                        stA + (uint32_t)((mwarp + mt * 16) * PITCH + ks * 8 + rpA) * 4);
#pragma unroll
            for (int ntp = 0; ntp < 4; ntp++)
                LDSM_X4(bf[2 * ntp][0], bf[2 * ntp][1], bf[2 * ntp + 1][0], bf[2 * ntp + 1][1],
                        stW + (uint32_t)((nwarp + ntp * 16) * PITCH + ks * 8 + rpB) * 4);
#pragma unroll
            for (int mt = 0; mt < 4; mt++)
#pragma unroll
                for (int nt = 0; nt < 8; nt++)
                    mma_u(acc[mt][nt], af[mt], bf[nt][0], bf[nt][1]);
        }
    }

#pragma unroll
    for (int mt = 0; mt < 4; mt++) {
        const int r0 = rowBase + mwarp + mt * 16 + lr;
#pragma unroll
        for (int nt = 0; nt < 8; nt++) {
            const int c0 = colBase + nwarp + nt * 8 + lc * 2;
            const float bb0 = __ldg(&bias[c0]);
            const float bb1 = __ldg(&bias[c0 + 1]);
            float2 v0 = { acc[mt][nt][0] + bb0, acc[mt][nt][1] + bb1 };
            float2 v1 = { acc[mt][nt][2] + bb0, acc[mt][nt][3] + bb1 };
            *reinterpret_cast<float2*>(&C[(size_t)r0 * H + c0])       = v0;
            *reinterpret_cast<float2*>(&C[(size_t)(r0 + 8) * H + c0]) = v1;
        }
    }
}

// ============================================================
// Attention: tensor-core S=QK^T and P*V, ldmatrix for Q/K/P
// fragments, compacted keys, fp32 softmax + poly exp2.
// 128 thr (4 warps), 64 q-rows/block. grid = (8, 12, 16).
// ============================================================
#define QP 68
#define VP 72
#define ATT_SMEM ((64 * QP * 2 + 64 * VP) * 4 + T_ * 4)

extern __shared__ float asm_[];

__global__ __launch_bounds__(128)
void attn_kernel(const float* __restrict__ Q, const float* __restrict__ K,
                 const float* __restrict__ V, float* __restrict__ O) {
    float* sQ  = asm_;
    float* sKP = sQ + 64 * QP;
    float* sV  = sKP + 64 * QP;
    int*  sIdx = (int*)(sV + 64 * VP);

    const int qt = blockIdx.x;
    const int nh = blockIdx.y;
    const int b  = blockIdx.z;
    const int tid  = threadIdx.x;
    const int wid  = tid >> 5;
    const int lane = tid & 31;
    const int lr   = lane >> 2;
    const int lc   = lane & 3;
    const int qr   = wid * 16 + lr;

    const uint32_t aQ  = smem_u32(sQ);
    const uint32_t aKP = smem_u32(sKP);
    const int rpA = (lane & 15) * QP + ((lane >> 4) << 2);
    const int rpB = ((lane & 7) + ((lane & 16) >> 1)) * QP + ((lane & 8) >> 1);

    const int vcnt = g_vcnt[b];
    for (int i = tid; i < T_; i += 128) sIdx[i] = g_idx[b * T_ + i];

    const float* Qb = Q + (size_t)(b * T_ + qt * 64) * H + nh * HD_;
    const float* Kb = K + (size_t)(b * T_) * H + nh * HD_;
    const float* Vb = V + (size_t)(b * T_) * H + nh * HD_;

#pragma unroll
    for (int it = 0; it < 16; it++) {
        int e = tid + it * 128;
        int row = e >> 5, c2 = (e & 31) << 1;
        float2 v = *reinterpret_cast<const float2*>(&Qb[row * H + c2]);
        float2 o = { rna_tf32(v.x * 0.125f), rna_tf32(v.y * 0.125f) };
        *reinterpret_cast<float2*>(&sQ[row * QP + c2]) = o;
    }
    __syncthreads();

    uint32_t aq[8][4];
#pragma unroll
    for (int ks = 0; ks < 8; ks++)
        LDSM_X4(aq[ks][0], aq[ks][1], aq[ks][2], aq[ks][3],
                aQ + (uint32_t)(wid * 16 * QP + ks * 8 + rpA) * 4);

    float m0 = -1e30f, m1 = -1e30f, l0 = 0.f, l1 = 0.f;
    float accO[8][4];
#pragma unroll
    for (int nt = 0; nt < 8; nt++)
#pragma unroll
        for (int i = 0; i < 4; i++) accO[nt][i] = 0.f;

    const int ntiles = (vcnt + 63) >> 6;
    for (int kt = 0; kt < ntiles; kt++) {
        __syncthreads();
        const int base = kt << 6;
        const int nval = min(64, vcnt - base);

#pragma unroll
        for (int it = 0; it < 16; it++) {
            int e = tid + it * 128;
            int row = e >> 5, c2 = (e & 31) << 1;
            int grow = sIdx[base + ((row < nval) ? row : 0)];
            float2 kv = *reinterpret_cast<const float2*>(&Kb[(size_t)grow * H + c2]);
            float2 vv = *reinterpret_cast<const float2*>(&Vb[(size_t)grow * H + c2]);
            float2 ko = { rna_tf32(kv.x), rna_tf32(kv.y) };
            float2 vo = { rna_tf32(vv.x), rna_tf32(vv.y) };
            *reinterpret_cast<float2*>(&sKP[row * QP + c2]) = ko;
            *reinterpret_cast<float2*>(&sV[row * VP + c2])  = vo;
        }
        __syncthreads();

        float s[8][4];
#pragma unroll
        for (int nt = 0; nt < 8; nt++)
#pragma unroll
            for (int i = 0; i < 4; i++) s[nt][i] = 0.f;
#pragma unroll
        for (int ks = 0; ks < 8; ks++) {
#pragma unroll
            for (int ntp = 0; ntp < 4; ntp++) {
                uint32_t b00, b01, b10, b11;
                LDSM_X4(b00, b01, b10, b11,
                        aKP + (uint32_t)(ntp * 16 * QP + ks * 8 + rpB) * 4);
                mma_u(s[2 * ntp],     aq[ks], b00, b01);
                mma_u(s[2 * ntp + 1], aq[ks], b10, b11);
            }
        }

#pragma unroll
        for (int nt = 0; nt < 8; nt++) {
            const int c = nt * 8 + 2 * lc;
            if (c     >= nval) { s[nt][0] = -1e9f; s[nt][2] = -1e9f; }
            if (c + 1 >= nval) { s[nt][1] = -1e9f; s[nt][3] = -1e9f; }
        }

        float mx0 = s[0][0], mx1 = s[0][2];
#pragma unroll
        for (int nt = 0; nt < 8; nt++) {
            mx0 = fmaxf(mx0, fmaxf(s[nt][0], s[nt][1]));
            mx1 = fmaxf(mx1, fmaxf(s[nt][2], s[nt][3]));
        }
        mx0 = fmaxf(mx0, __shfl_xor_sync(0xffffffffu, mx0, 1));
        mx0 = fmaxf(mx0, __shfl_xor_sync(0xffffffffu, mx0, 2));
        mx1 = fmaxf(mx1, __shfl_xor_sync(0xffffffffu, mx1, 1));
        mx1 = fmaxf(mx1, __shfl_xor_sync(0xffffffffu, mx1, 2));

        float mn0 = fmaxf(m0, mx0), mn1 = fmaxf(m1, mx1);
        float cr0 = exp2p((m0 - mn0) * LOG2E);
        float cr1 = exp2p((m1 - mn1) * LOG2E);
        m0 = mn0; m1 = mn1;

        float ps0 = 0.f, ps1 = 0.f;
#pragma unroll
        for (int nt = 0; nt < 8; nt++) {
            s[nt][0] = exp2p((s[nt][0] - mn0) * LOG2E);
            s[nt][1] = exp2p((s[nt][1] - mn0) * LOG2E);
            s[nt][2] = exp2p((s[nt][2] - mn1) * LOG2E);
            s[nt][3] = exp2p((s[nt][3] - mn1) * LOG2E);
            ps0 += s[nt][0] + s[nt][1];
            ps1 += s[nt][2] + s[nt][3];
        }
        ps0 += __shfl_xor_sync(0xffffffffu, ps0, 1);
        ps0 += __shfl_xor_sync(0xffffffffu, ps0, 2);
        ps1 += __shfl_xor_sync(0xffffffffu, ps1, 1);
        ps1 += __shfl_xor_sync(0xffffffffu, ps1, 2);
        l0 = l0 * cr0 + ps0;
        l1 = l1 * cr1 + ps1;
#pragma unroll
        for (int nt = 0; nt < 8; nt++) {
            accO[nt][0] *= cr0; accO[nt][1] *= cr0;
            accO[nt][2] *= cr1; accO[nt][3] *= cr1;
        }

        __syncthreads();

#pragma unroll
        for (int nt = 0; nt < 8; nt++) {
            const int c = nt * 8 + 2 * lc;
            float2 p0 = { rna_tf32(s[nt][0]), rna_tf32(s[nt][1]) };
            float2 p1 = { rna_tf32(s[nt][2]), rna_tf32(s[nt][3]) };
            *reinterpret_cast<float2*>(&sKP[qr * QP + c])       = p0;
            *reinterpret_cast<float2*>(&sKP[(qr + 8) * QP + c]) = p1;
        }
        __syncwarp();

        uint32_t ap[8][4];
#pragma unroll
        for (int ks = 0; ks < 8; ks++)
            LDSM_X4(ap[ks][0], ap[ks][1], ap[ks][2], ap[ks][3],
                    aKP + (uint32_t)(wid * 16 * QP + ks * 8 + rpA) * 4);

#pragma unroll
        for (int nt = 0; nt < 8; nt++) {
            const int n0 = nt * 8 + lr;
#pragma unroll
            for (int ks = 0; ks < 8; ks++) {
                const int k0 = ks * 8;
                uint32_t bv0 = __float_as_uint(sV[(k0 + lc) * VP + n0]);
                uint32_t bv1 = __float_as_uint(sV[(k0 + lc + 4) * VP + n0]);
                mma_u(accO[nt], ap[ks], bv0, bv1);
            }
        }
    }

    float* Ob = O + (size_t)(b * T_ + qt * 64) * H + nh * HD_;
    const float i0 = 1.0f / l0, i1 = 1.0f / l1;
#pragma unroll
    for (int nt = 0; nt < 8; nt++) {
        const int c = nt * 8 + 2 * lc;
        float2 o0 = { rna_tf32(accO[nt][0] * i0), rna_tf32(accO[nt][1] * i0) };
        float2 o1 = { rna_tf32(accO[nt][2] * i1), rna_tf32(accO[nt][3] * i1) };
        *reinterpret_cast<float2*>(&Ob[qr * H + c])       = o0;
        *reinterpret_cast<float2*>(&Ob[(qr + 8) * H + c]) = o1;
    }
}

// ============================================================
// launch
// ============================================================
extern "C" void kernel_launch(void* const* d_in, const int* in_sizes, int n_in,
                              void* d_out, int out_size) {
    (void)in_sizes; (void)n_in; (void)out_size;
    const float* x  = (const float*)d_in[0];
    const int*  mask = (const int*) d_in[1];
    const float* Wq = (const float*)d_in[2];
    const float* bq = (const float*)d_in[3];
    const float* Aq = (const float*)d_in[4];
    const float* Bq = (const float*)d_in[5];
    const float* Wk = (const float*)d_in[6];
    const float* bk = (const float*)d_in[7];
    const float* Wv = (const float*)d_in[8];
    const float* bv = (const float*)d_in[9];
    const float* Av = (const float*)d_in[10];
    const float* Bv = (const float*)d_in[11];
    const float* Wo = (const float*)d_in[12];
    const float* bo = (const float*)d_in[13];
    float* out = (float*)d_out;

    float *pxt, *pweff_q, *pweff_v, *pwkt, *pwot, *pq, *pk, *pv, *pao;
    cudaGetSymbolAddress((void**)&pxt, g_xt);
    cudaGetSymbolAddress((void**)&pweff_q, g_weff_q);
    cudaGetSymbolAddress((void**)&pweff_v, g_weff_v);
    cudaGetSymbolAddress((void**)&pwkt, g_wkt);
    cudaGetSymbolAddress((void**)&pwot, g_wot);
    cudaGetSymbolAddress((void**)&pq, g_q);
    cudaGetSymbolAddress((void**)&pk, g_k);
    cudaGetSymbolAddress((void**)&pv, g_v);
    cudaGetSymbolAddress((void**)&pao, g_ao);

    static bool attr_set = false;
    if (!attr_set) {
        cudaFuncSetAttribute(gemm_mma,
            cudaFuncAttributeMaxDynamicSharedMemorySize, GEMM_SMEM);
        cudaFuncSetAttribute(attn_kernel,
            cudaFuncAttributeMaxDynamicSharedMemorySize, ATT_SMEM);
        attr_set = true;
    }

    prep_kernel<<<XBLK + 4 * WBLK + B_, 256>>>(
        x, Wk, Wo, Wq, Aq, Bq, Wv, Av, Bv, mask);

    gemm_mma<<<dim3(18, NROWS / 128), 128, GEMM_SMEM>>>(
        pxt, pweff_q, pwkt, pweff_v, bq, bk, bv, pq, pk, pv);

    attn_kernel<<<dim3(T_ / 64, NH_, B_), 128, ATT_SMEM>>>(pq, pk, pv, pao);

    gemm_mma<<<dim3(6, NROWS / 128), 128, GEMM_SMEM>>>(
        pao, pwot, pwot, pwot, bo, bo, bo, out, out, out);
}

// round 9
// speedup vs baseline: 2.7393x; 1.3880x over previous
#include <cuda_runtime.h>
#include <cstdint>

#define H   768
#define NH_ 12
#define HD_ 64
#define B_  16
#define T_  512
#define NROWS (B_ * T_)
#define SCALING 2.0f

// -------- device scratch --------
__device__ float g_xt  [(size_t)NROWS * H];   // x, tf32-rounded (all rows)
__device__ float g_xkv [(size_t)NROWS * H];   // x rows compacted by mask, tf32
__device__ float g_weff_q[H * H];
__device__ float g_weff_v[H * H];
__device__ float g_wkt [H * H];
__device__ float g_wot [H * H];
__device__ float g_q [(size_t)NROWS * H];
__device__ float g_k [(size_t)NROWS * H];     // compacted rows per batch
__device__ float g_v [(size_t)NROWS * H];     // compacted rows per batch
__device__ float g_ao[(size_t)NROWS * H];
__device__ int   g_idx[B_ * T_];
__device__ int   g_vcnt[B_];

// ============================================================
// helpers
// ============================================================
__device__ __forceinline__ float rna_tf32(float x) {
    uint32_t u;
    asm("cvt.rna.tf32.f32 %0, %1;" : "=r"(u) : "f"(x));
    return __uint_as_float(u);
}

__device__ __forceinline__ void mma_u(float* d, const uint32_t* a,
                                      uint32_t b0, uint32_t b1) {
    asm volatile(
        "mma.sync.aligned.m16n8k8.row.col.f32.tf32.tf32.f32 "
        "{%0,%1,%2,%3}, {%4,%5,%6,%7}, {%8,%9}, {%0,%1,%2,%3};"
        : "+f"(d[0]), "+f"(d[1]), "+f"(d[2]), "+f"(d[3])
        : "r"(a[0]), "r"(a[1]), "r"(a[2]), "r"(a[3]), "r"(b0), "r"(b1));
}

__device__ __forceinline__ uint32_t smem_u32(const void* p) {
    uint32_t a;
    asm("{ .reg .u64 t; cvta.to.shared.u64 t, %1; cvt.u32.u64 %0, t; }"
        : "=r"(a) : "l"(p));
    return a;
}

#define LDSM_X4(d0, d1, d2, d3, addr)                                        \
    asm volatile("ldmatrix.sync.aligned.m8n8.x4.shared.b16 {%0,%1,%2,%3}, [%4];" \
        : "=r"(d0), "=r"(d1), "=r"(d2), "=r"(d3) : "r"(addr))

__device__ __forceinline__ void cp_async16(uint32_t dst, const void* src) {
    asm volatile("cp.async.ca.shared.global [%0], [%1], 16;" :: "r"(dst), "l"(src));
}
#define CP_COMMIT() asm volatile("cp.async.commit_group;" ::: "memory")
#define CP_WAIT(n)  asm volatile("cp.async.wait_group %0;" :: "n"(n) : "memory")

// polynomial 2^t for t <= 0 (FMA pipe). rel err ~1e-5.
__device__ __forceinline__ float exp2p(float t) {
    t = fmaxf(t, -126.f);
    float fi = floorf(t);
    float f  = t - fi;
    float p  = 0.0001540353f;
    p = fmaf(p, f, 0.0013333558f);
    p = fmaf(p, f, 0.0096181291f);
    p = fmaf(p, f, 0.0555041087f);
    p = fmaf(p, f, 0.2402265070f);
    p = fmaf(p, f, 0.6931471806f);
    p = fmaf(p, f, 1.0f);
    int ei = (int)fi;
    return p * __int_as_float((ei + 127) << 23);
}
#define LOG2E 1.4426950408889634f

// ============================================================
// fused prep (vectorized): cvt x/Wk/Wo, weff q/v, compaction
// ============================================================
#define XB4   (NROWS * H / 1024)   // 6144 blocks (float4 per thread)
#define WB4   (H * H / 1024)       // 576
#define WBLK  (H * H / 256)        // 2304

__global__ __launch_bounds__(256)
void prep_kernel(const float* __restrict__ x,
                 const float* __restrict__ Wk, const float* __restrict__ Wo,
                 const float* __restrict__ Wq, const float* __restrict__ Aq,
                 const float* __restrict__ Bq,
                 const float* __restrict__ Wv, const float* __restrict__ Av,
                 const float* __restrict__ Bv,
                 const int* __restrict__ mask) {
    int bx = blockIdx.x;
    if (bx < XB4) {
        int i = bx * 256 + threadIdx.x;
        float4 v = reinterpret_cast<const float4*>(x)[i];
        v.x = rna_tf32(v.x); v.y = rna_tf32(v.y);
        v.z = rna_tf32(v.z); v.w = rna_tf32(v.w);
        reinterpret_cast<float4*>(g_xt)[i] = v;
        return;
    }
    bx -= XB4;
    if (bx < 2 * WB4) {
        const bool isK = bx < WB4;
        int i = (isK ? bx : bx - WB4) * 256 + threadIdx.x;
        float4 v = reinterpret_cast<const float4*>(isK ? Wk : Wo)[i];
        v.x = rna_tf32(v.x); v.y = rna_tf32(v.y);
        v.z = rna_tf32(v.z); v.w = rna_tf32(v.w);
        reinterpret_cast<float4*>(isK ? g_wkt : g_wot)[i] = v;
        return;
    }
    bx -= 2 * WB4;
    if (bx < 2 * WBLK) {
        const bool isQ = bx < WBLK;
        int idx = (isQ ? bx : bx - WBLK) * 256 + threadIdx.x;
        int j = idx / H, h = idx % H;
        const float* W  = isQ ? Wq : Wv;
        const float* A  = isQ ? Aq : Av;
        const float* Bm = isQ ? Bq : Bv;
        float acc = W[idx];
#pragma unroll
        for (int r = 0; r < 4; r++)
            acc = fmaf(SCALING * Bm[j * 4 + r], A[r * H + h], acc);
        (isQ ? g_weff_q : g_weff_v)[idx] = rna_tf32(acc);
        return;
    }
    bx -= 2 * WBLK;
    if (threadIdx.x < 32) {
        int b = bx;
        int lane = threadIdx.x;
        int base = 0;
        for (int c = 0; c < T_ / 32; c++) {
            int key = c * 32 + lane;
            int v = (mask[b * T_ + key] != 0);
            unsigned bal = __ballot_sync(0xffffffffu, v);
            int pos = base + __popc(bal & ((1u << lane) - 1u));
            if (v) g_idx[b * T_ + pos] = key;
            base += __popc(bal);
        }
        if (lane == 0) g_vcnt[b] = base;
    }
}

// ============================================================
// gather compacted x rows for K/V projections (tf32-rounded).
// grid (64, B_); 256 thr = 8 warps, one row each (8 rows/block).
// ============================================================
__global__ __launch_bounds__(256)
void gather_kernel(const float* __restrict__ x) {
    const int b = blockIdx.y;
    const int vcnt = g_vcnt[b];
    const int r    = threadIdx.x >> 5;
    const int lane = threadIdx.x & 31;
    const int row  = blockIdx.x * 8 + r;
    if (row >= vcnt) return;
    const int grow = g_idx[b * T_ + row];
    const float* src = x + (size_t)(b * T_ + grow) * H;
    float* dst = g_xkv + (size_t)(b * T_ + row) * H;
#pragma unroll
    for (int k = 0; k < 6; k++) {
        float4 v = *reinterpret_cast<const float4*>(src + lane * 4 + k * 128);
        v.x = rna_tf32(v.x); v.y = rna_tf32(v.y);
        v.z = rna_tf32(v.z); v.w = rna_tf32(v.w);
        *reinterpret_cast<float4*>(dst + lane * 4 + k * 128) = v;
    }
}

// ============================================================
// tf32 GEMM: 128x128 CTA tile, 4 warps @ 64x64 each, BK=16,
// ldmatrix fragments, 3-stage cp.async, 1 sync/iter, 128 thr.
// sel = blockIdx.x/6: 0 -> A (all rows), 1/2 -> g_xkv with
// early exit past vcnt (K/V projections over valid keys only).
// ============================================================
#define PITCH 20
#define NITER (H / 16)            // 48
#define STG_FLTS (128 * PITCH)
#define STAGE_FLTS (2 * STG_FLTS)
#define GEMM_SMEM (3 * STAGE_FLTS * 4)   // 61440 B

extern __shared__ float gsm[];

__global__ __launch_bounds__(128, 1)
void gemm_mma(const float* __restrict__ A,
              const float* W0, const float* W1, const float* W2,
              const float* b0, const float* b1, const float* b2,
              float* C0, float* C1, float* C2) {
    const int sel = blockIdx.x / 6;
    const int rowBase = blockIdx.y * 128;
    // K/V projections: skip row-blocks entirely past this batch's key count
    if (sel != 0 && (rowBase & (T_ - 1)) >= g_vcnt[rowBase >> 9]) return;

    const float* Aact = (sel == 0) ? A : g_xkv;
    const float* W    = (sel == 0) ? W0 : (sel == 1) ? W1 : W2;
    const float* bias = (sel == 0) ? b0 : (sel == 1) ? b1 : b2;
    float*       C    = (sel == 0) ? C0 : (sel == 1) ? C1 : C2;

    const int tid  = threadIdx.x;
    const int wid  = tid >> 5;
    const int lane = tid & 31;
    const int lr   = lane >> 2;
    const int lc   = lane & 3;
    const int colBase = (blockIdx.x % 6) * 128;
    const int mwarp = (wid & 1) * 64;
    const int nwarp = (wid >> 1) * 64;

    const uint32_t sb = smem_u32(gsm);

    int rowi[4], c4i[4];
#pragma unroll
    for (int i = 0; i < 4; i++) {
        int e = tid + i * 128;
        rowi[i] = e >> 2;
        c4i[i]  = (e & 3) << 2;
    }

    const int rpA = (lane & 15) * PITCH + ((lane >> 4) << 2);
    const int rpB = ((lane & 7) + ((lane & 16) >> 1)) * PITCH + ((lane & 8) >> 1);

    float acc[4][8][4];
#pragma unroll
    for (int mt = 0; mt < 4; mt++)
#pragma unroll
        for (int nt = 0; nt < 8; nt++)
#pragma unroll
            for (int i = 0; i < 4; i++) acc[mt][nt][i] = 0.f;

    auto load_stage = [&](int it, int st) {
        const int koff = it * 16;
        const uint32_t base = sb + (uint32_t)(st * STAGE_FLTS) * 4;
#pragma unroll
        for (int i = 0; i < 4; i++) {
            cp_async16(base + (uint32_t)(rowi[i] * PITCH + c4i[i]) * 4,
                       Aact + (size_t)(rowBase + rowi[i]) * H + koff + c4i[i]);
            cp_async16(base + (uint32_t)(STG_FLTS + rowi[i] * PITCH + c4i[i]) * 4,
                       W + (size_t)(colBase + rowi[i]) * H + koff + c4i[i]);
        }
        CP_COMMIT();
    };

    load_stage(0, 0);
    load_stage(1, 1);

    for (int it = 0; it < NITER; it++) {
        if (it + 1 < NITER) { CP_WAIT(1); } else { CP_WAIT(0); }
        __syncthreads();
        if (it + 2 < NITER) load_stage(it + 2, (it + 2) % 3);

        const uint32_t stA = sb + (uint32_t)((it % 3) * STAGE_FLTS) * 4;
        const uint32_t stW = stA + (uint32_t)STG_FLTS * 4;
#pragma unroll
        for (int ks = 0; ks < 2; ks++) {
            uint32_t af[4][4], bf[8][2];
#pragma unroll
            for (int mt = 0; mt < 4; mt++)
                LDSM_X4(af[mt][0], af[mt][1], af[mt][2], af[mt][3],
                        stA + (uint32_t)((mwarp + mt * 16) * PITCH + ks * 8 + rpA) * 4);
#pragma unroll
            for (int ntp = 0; ntp < 4; ntp++)
                LDSM_X4(bf[2 * ntp][0], bf[2 * ntp][1], bf[2 * ntp + 1][0], bf[2 * ntp + 1][1],
                        stW + (uint32_t)((nwarp + ntp * 16) * PITCH + ks * 8 + rpB) * 4);
#pragma unroll
            for (int mt = 0; mt < 4; mt++)
#pragma unroll
                for (int nt = 0; nt < 8; nt++)
                    mma_u(acc[mt][nt], af[mt], bf[nt][0], bf[nt][1]);
        }
    }

#pragma unroll
    for (int mt = 0; mt < 4; mt++) {
        const int r0 = rowBase + mwarp + mt * 16 + lr;
#pragma unroll
        for (int nt = 0; nt < 8; nt++) {
            const int c0 = colBase + nwarp + nt * 8 + lc * 2;
            const float bb0 = __ldg(&bias[c0]);
            const float bb1 = __ldg(&bias[c0 + 1]);
            float2 v0 = { acc[mt][nt][0] + bb0, acc[mt][nt][1] + bb1 };
            float2 v1 = { acc[mt][nt][2] + bb0, acc[mt][nt][3] + bb1 };
            *reinterpret_cast<float2*>(&C[(size_t)r0 * H + c0])       = v0;
            *reinterpret_cast<float2*>(&C[(size_t)(r0 + 8) * H + c0]) = v1;
        }
    }
}

// ============================================================
// Attention: tensor-core S=QK^T and P*V; K/V pre-compacted so
// loads are contiguous. fp32 softmax + poly exp2.
// 128 thr (4 warps), 64 q-rows/block. grid = (8, 12, 16).
// ============================================================
#define QP 68
#define VP 72
#define ATT_SMEM ((64 * QP * 2 + 64 * VP) * 4)

extern __shared__ float asm_[];

__global__ __launch_bounds__(128)
void attn_kernel(const float* __restrict__ Q, const float* __restrict__ K,
                 const float* __restrict__ V, float* __restrict__ O) {
    float* sQ  = asm_;
    float* sKP = sQ + 64 * QP;
    float* sV  = sKP + 64 * QP;

    const int qt = blockIdx.x;
    const int nh = blockIdx.y;
    const int b  = blockIdx.z;
    const int tid  = threadIdx.x;
    const int wid  = tid >> 5;
    const int lane = tid & 31;
    const int lr   = lane >> 2;
    const int lc   = lane & 3;
    const int qr   = wid * 16 + lr;

    const uint32_t aQ  = smem_u32(sQ);
    const uint32_t aKP = smem_u32(sKP);
    const int rpA = (lane & 15) * QP + ((lane >> 4) << 2);
    const int rpB = ((lane & 7) + ((lane & 16) >> 1)) * QP + ((lane & 8) >> 1);

    const int vcnt = g_vcnt[b];

    const float* Qb = Q + (size_t)(b * T_ + qt * 64) * H + nh * HD_;
    const float* Kb = K + (size_t)(b * T_) * H + nh * HD_;
    const float* Vb = V + (size_t)(b * T_) * H + nh * HD_;

#pragma unroll
    for (int it = 0; it < 16; it++) {
        int e = tid + it * 128;
        int row = e >> 5, c2 = (e & 31) << 1;
        float2 v = *reinterpret_cast<const float2*>(&Qb[row * H + c2]);
        float2 o = { rna_tf32(v.x * 0.125f), rna_tf32(v.y * 0.125f) };
        *reinterpret_cast<float2*>(&sQ[row * QP + c2]) = o;
    }
    __syncthreads();

    uint32_t aq[8][4];
#pragma unroll
    for (int ks = 0; ks < 8; ks++)
        LDSM_X4(aq[ks][0], aq[ks][1], aq[ks][2], aq[ks][3],
                aQ + (uint32_t)(wid * 16 * QP + ks * 8 + rpA) * 4);

    float m0 = -1e30f, m1 = -1e30f, l0 = 0.f, l1 = 0.f;
    float accO[8][4];
#pragma unroll
    for (int nt = 0; nt < 8; nt++)
#pragma unroll
        for (int i = 0; i < 4; i++) accO[nt][i] = 0.f;

    const int ntiles = (vcnt + 63) >> 6;
    for (int kt = 0; kt < ntiles; kt++) {
        __syncthreads();
        const int base = kt << 6;
        const int nval = min(64, vcnt - base);

        // contiguous K/V loads (rows already compacted & tf32-rounded)
#pragma unroll
        for (int it = 0; it < 16; it++) {
            int e = tid + it * 128;
            int row = e >> 5, c2 = (e & 31) << 1;
            int grow = base + ((row < nval) ? row : 0);
            float2 ko = *reinterpret_cast<const float2*>(&Kb[(size_t)grow * H + c2]);
            float2 vo = *reinterpret_cast<const float2*>(&Vb[(size_t)grow * H + c2]);
            *reinterpret_cast<float2*>(&sKP[row * QP + c2]) = ko;
            *reinterpret_cast<float2*>(&sV[row * VP + c2])  = vo;
        }
        __syncthreads();

        float s[8][4];
#pragma unroll
        for (int nt = 0; nt < 8; nt++)
#pragma unroll
            for (int i = 0; i < 4; i++) s[nt][i] = 0.f;
#pragma unroll
        for (int ks = 0; ks < 8; ks++) {
#pragma unroll
            for (int ntp = 0; ntp < 4; ntp++) {
                uint32_t b00, b01, b10, b11;
                LDSM_X4(b00, b01, b10, b11,
                        aKP + (uint32_t)(ntp * 16 * QP + ks * 8 + rpB) * 4);
                mma_u(s[2 * ntp],     aq[ks], b00, b01);
                mma_u(s[2 * ntp + 1], aq[ks], b10, b11);
            }
        }

#pragma unroll
        for (int nt = 0; nt < 8; nt++) {
            const int c = nt * 8 + 2 * lc;
            if (c     >= nval) { s[nt][0] = -1e9f; s[nt][2] = -1e9f; }
            if (c + 1 >= nval) { s[nt][1] = -1e9f; s[nt][3] = -1e9f; }
        }

        float mx0 = s[0][0], mx1 = s[0][2];
#pragma unroll
        for (int nt = 0; nt < 8; nt++) {
            mx0 = fmaxf(mx0, fmaxf(s[nt][0], s[nt][1]));
            mx1 = fmaxf(mx1, fmaxf(s[nt][2], s[nt][3]));
        }
        mx0 = fmaxf(mx0, __shfl_xor_sync(0xffffffffu, mx0, 1));
        mx0 = fmaxf(mx0, __shfl_xor_sync(0xffffffffu, mx0, 2));
        mx1 = fmaxf(mx1, __shfl_xor_sync(0xffffffffu, mx1, 1));
        mx1 = fmaxf(mx1, __shfl_xor_sync(0xffffffffu, mx1, 2));

        float mn0 = fmaxf(m0, mx0), mn1 = fmaxf(m1, mx1);
        float cr0 = exp2p((m0 - mn0) * LOG2E);
        float cr1 = exp2p((m1 - mn1) * LOG2E);
        m0 = mn0; m1 = mn1;

        float ps0 = 0.f, ps1 = 0.f;
#pragma unroll
        for (int nt = 0; nt < 8; nt++) {
            s[nt][0] = exp2p((s[nt][0] - mn0) * LOG2E);
            s[nt][1] = exp2p((s[nt][1] - mn0) * LOG2E);
            s[nt][2] = exp2p((s[nt][2] - mn1) * LOG2E);
            s[nt][3] = exp2p((s[nt][3] - mn1) * LOG2E);
            ps0 += s[nt][0] + s[nt][1];
            ps1 += s[nt][2] + s[nt][3];
        }
        ps0 += __shfl_xor_sync(0xffffffffu, ps0, 1);
        ps0 += __shfl_xor_sync(0xffffffffu, ps0, 2);
        ps1 += __shfl_xor_sync(0xffffffffu, ps1, 1);
        ps1 += __shfl_xor_sync(0xffffffffu, ps1, 2);
        l0 = l0 * cr0 + ps0;
        l1 = l1 * cr1 + ps1;
#pragma unroll
        for (int nt = 0; nt < 8; nt++) {
            accO[nt][0] *= cr0; accO[nt][1] *= cr0;
            accO[nt][2] *= cr1; accO[nt][3] *= cr1;
        }

        __syncthreads();

#pragma unroll
        for (int nt = 0; nt < 8; nt++) {
            const int c = nt * 8 + 2 * lc;
            float2 p0 = { rna_tf32(s[nt][0]), rna_tf32(s[nt][1]) };
            float2 p1 = { rna_tf32(s[nt][2]), rna_tf32(s[nt][3]) };
            *reinterpret_cast<float2*>(&sKP[qr * QP + c])       = p0;
            *reinterpret_cast<float2*>(&sKP[(qr + 8) * QP + c]) = p1;
        }
        __syncwarp();

        uint32_t ap[8][4];
#pragma unroll
        for (int ks = 0; ks < 8; ks++)
            LDSM_X4(ap[ks][0], ap[ks][1], ap[ks][2], ap[ks][3],
                    aKP + (uint32_t)(wid * 16 * QP + ks * 8 + rpA) * 4);

#pragma unroll
        for (int nt = 0; nt < 8; nt++) {
            const int n0 = nt * 8 + lr;
#pragma unroll
            for (int ks = 0; ks < 8; ks++) {
                const int k0 = ks * 8;
                uint32_t bv0 = __float_as_uint(sV[(k0 + lc) * VP + n0]);
                uint32_t bv1 = __float_as_uint(sV[(k0 + lc + 4) * VP + n0]);
                mma_u(accO[nt], ap[ks], bv0, bv1);
            }
        }
    }

    float* Ob = O + (size_t)(b * T_ + qt * 64) * H + nh * HD_;
    const float i0 = 1.0f / l0, i1 = 1.0f / l1;
#pragma unroll
    for (int nt = 0; nt < 8; nt++) {
        const int c = nt * 8 + 2 * lc;
        float2 o0 = { rna_tf32(accO[nt][0] * i0), rna_tf32(accO[nt][1] * i0) };
        float2 o1 = { rna_tf32(accO[nt][2] * i1), rna_tf32(accO[nt][3] * i1) };
        *reinterpret_cast<float2*>(&Ob[qr * H + c])       = o0;
        *reinterpret_cast<float2*>(&Ob[(qr + 8) * H + c]) = o1;
    }
}

// ============================================================
// launch
// ============================================================
extern "C" void kernel_launch(void* const* d_in, const int* in_sizes, int n_in,
                              void* d_out, int out_size) {
    (void)in_sizes; (void)n_in; (void)out_size;
    const float* x  = (const float*)d_in[0];
    const int*  mask = (const int*) d_in[1];
    const float* Wq = (const float*)d_in[2];
    const float* bq = (const float*)d_in[3];
    const float* Aq = (const float*)d_in[4];
    const float* Bq = (const float*)d_in[5];
    const float* Wk = (const float*)d_in[6];
    const float* bk = (const float*)d_in[7];
    const float* Wv = (const float*)d_in[8];
    const float* bv = (const float*)d_in[9];
    const float* Av = (const float*)d_in[10];
    const float* Bv = (const float*)d_in[11];
    const float* Wo = (const float*)d_in[12];
    const float* bo = (const float*)d_in[13];
    float* out = (float*)d_out;

    float *pxt, *pweff_q, *pweff_v, *pwkt, *pwot, *pq, *pk, *pv, *pao;
    cudaGetSymbolAddress((void**)&pxt, g_xt);
    cudaGetSymbolAddress((void**)&pweff_q, g_weff_q);
    cudaGetSymbolAddress((void**)&pweff_v, g_weff_v);
    cudaGetSymbolAddress((void**)&pwkt, g_wkt);
    cudaGetSymbolAddress((void**)&pwot, g_wot);
    cudaGetSymbolAddress((void**)&pq, g_q);
    cudaGetSymbolAddress((void**)&pk, g_k);
    cudaGetSymbolAddress((void**)&pv, g_v);
    cudaGetSymbolAddress((void**)&pao, g_ao);

    static bool attr_set = false;
    if (!attr_set) {
        cudaFuncSetAttribute(gemm_mma,
            cudaFuncAttributeMaxDynamicSharedMemorySize, GEMM_SMEM);
        cudaFuncSetAttribute(attn_kernel,
            cudaFuncAttributeMaxDynamicSharedMemorySize, ATT_SMEM);
        attr_set = true;
    }

    prep_kernel<<<XB4 + 2 * WB4 + 2 * WBLK + B_, 256>>>(
        x, Wk, Wo, Wq, Aq, Bq, Wv, Av, Bv, mask);

    gather_kernel<<<dim3(64, B_), 256>>>(x);

    // Q over all rows; K/V over compacted rows with early exit
    gemm_mma<<<dim3(18, NROWS / 128), 128, GEMM_SMEM>>>(
        pxt, pweff_q, pwkt, pweff_v, bq, bk, bv, pq, pk, pv);

    attn_kernel<<<dim3(T_ / 64, NH_, B_), 128, ATT_SMEM>>>(pq, pk, pv, pao);

    gemm_mma<<<dim3(6, NROWS / 128), 128, GEMM_SMEM>>>(
        pao, pwot, pwot, pwot, bo, bo, bo, out, out, out);
}